// round 9
// baseline (speedup 1.0000x reference)
#include <cuda_runtime.h>
#include <cstdint>

#define BB   32
#define NN   512
#define DD   256
#define HH   8
#define HDIM 32
#define EE   16384
#define ETOT (EE + NN)

// ---------------- scratch (static device globals; no allocation) -------------
__device__ float    g_xwq[BB * NN * DD];
__device__ float    g_xwk[BB * NN * DD];
__device__ float    g_xwv[BB * NN * DD];
__device__ float    g_Q  [BB * NN * DD];
__device__ float    g_K  [BB * NN * DD];
__device__ float    g_V  [BB * NN * DD];
__device__ float    g_att[BB * NN * DD];
__device__ int      g_rowptr[NN + 1];
__device__ int2     g_edge[ETOT];          // (src, norm-as-int)
__device__ uint32_t g_bmask[NN * 16];      // packed mask bits
__device__ float    g_A[NN * NN];          // dense normalized adjacency (tf32-rounded)

// ---------------- helpers -----------------------------------------------------
__device__ __forceinline__ uint32_t f2tf32(float f) {
    uint32_t r;
    asm("cvt.rna.tf32.f32 %0, %1;" : "=r"(r) : "f"(f));
    return r;
}
__device__ __forceinline__ void mma_tf32(float* c, const uint32_t* a,
                                         uint32_t b0, uint32_t b1) {
    asm volatile(
        "mma.sync.aligned.m16n8k8.row.col.f32.tf32.tf32.f32 "
        "{%0,%1,%2,%3}, {%4,%5,%6,%7}, {%8,%9}, {%0,%1,%2,%3};"
        : "+f"(c[0]), "+f"(c[1]), "+f"(c[2]), "+f"(c[3])
        : "r"(a[0]), "r"(a[1]), "r"(a[2]), "r"(a[3]), "r"(b0), "r"(b1));
}
__device__ __forceinline__ void cp16(uint32_t saddr, const void* g) {
    asm volatile("cp.async.ca.shared.global [%0], [%1], 16;"
                 :: "r"(saddr), "l"(g) : "memory");
}
#define CP_COMMIT() asm volatile("cp.async.commit_group;" ::: "memory")
#define CP_WAIT0()  asm volatile("cp.async.wait_group 0;" ::: "memory")

// ---------------- fused single-CTA graph prep + dense A (tf32) ----------------
__global__ __launch_bounds__(NN) void k_graph(const int* __restrict__ edge) {
    __shared__ int sdeg[NN];
    __shared__ int scnt[NN];
    __shared__ int srow[NN];
    __shared__ int ss[NN];
    __shared__ int se64;
    int t = threadIdx.x;

    if (t == 0) {
        int nz = 0;
        for (int i = 0; i < 64; i++) nz += (edge[2 * i + 1] != 0);
        se64 = (nz == 0) ? 1 : 0;
    }
    sdeg[t] = 0;
    scnt[t] = 0;
    __syncthreads();
    int e64 = se64;

    for (int e = t; e < ETOT; e += NN) {
        int dst = (e < EE) ? (e64 ? edge[2 * (EE + e)] : edge[EE + e]) : (e - EE);
        if (dst >= 0 && dst < NN) atomicAdd(&sdeg[dst], 1);
    }
    __syncthreads();

    ss[t] = sdeg[t];
    __syncthreads();
    for (int off = 1; off < NN; off <<= 1) {
        int v = (t >= off) ? ss[t - off] : 0;
        __syncthreads();
        ss[t] += v;
        __syncthreads();
    }
    srow[t] = ss[t] - sdeg[t];
    g_rowptr[t + 1] = ss[t];
    if (t == 0) g_rowptr[0] = 0;
    __syncthreads();

    for (int e = t; e < ETOT; e += NN) {
        int s, d;
        if (e < EE) {
            s = e64 ? edge[2 * e] : edge[e];
            d = e64 ? edge[2 * (EE + e)] : edge[EE + e];
        } else {
            s = e - EE; d = e - EE;
        }
        if (s < 0 || s >= NN || d < 0 || d >= NN) continue;
        float nm = rsqrtf((float)sdeg[s]) * rsqrtf((float)sdeg[d]);
        int pos = srow[d] + atomicAdd(&scnt[d], 1);
        g_edge[pos] = make_int2(s, __float_as_int(nm));
    }
    __syncthreads();

    // dense A row t: accumulate fp32 (deterministic), then round to tf32 once
    float4* arow4 = (float4*)(g_A + (size_t)t * NN);
    #pragma unroll 8
    for (int i = 0; i < NN / 4; i++) arow4[i] = make_float4(0.f, 0.f, 0.f, 0.f);
    float* arow = g_A + (size_t)t * NN;
    for (int i = srow[t]; i < ss[t]; i++) {
        int2 e = g_edge[i];
        arow[e.x] += __int_as_float(e.y);
    }
    for (int i = 0; i < NN; i++)
        arow[i] = __uint_as_float(f2tf32(arow[i]));
}

// ---------------- mask bit-packing --------------------------------------------
__global__ void k_pack(const int* __restrict__ mask) {
    int idx = blockIdx.x * 256 + threadIdx.x;   // 8192 words
    int r  = idx >> 4;
    int wd = idx & 15;
    const int* mrow = mask + (size_t)r * NN + wd * 32;
    uint32_t bits = 0;
    #pragma unroll
    for (int j = 0; j < 32; j++) bits |= (mrow[j] ? 1u : 0u) << j;
    g_bmask[idx] = bits;
}

// ---------------- tf32 mma.sync GEMM (projections / output) -------------------
#define AS_STRIDE 36
#define BS_STRIDE 132

__global__ __launch_bounds__(256) void k_gemm_mma(
    const float* __restrict__ a0p, const float* __restrict__ a1p,
    const float* __restrict__ a2p,
    const float* __restrict__ w0, const float* __restrict__ w1,
    const float* __restrict__ w2,
    float* __restrict__ c0p, float* __restrict__ c1p, float* __restrict__ c2p,
    const float* __restrict__ bias, int roundC)
{
    __shared__ uint32_t As[128 * AS_STRIDE];
    __shared__ uint32_t Bs[32 * BS_STRIDE];
    __shared__ float    bsh[128];

    const int z = blockIdx.z;
    const float* A  = (z == 0) ? a0p : (z == 1) ? a1p : a2p;
    const float* Wm = (z == 0) ? w0  : (z == 1) ? w1  : w2;
    float*       C  = (z == 0) ? c0p : (z == 1) ? c1p : c2p;

    const int n0 = blockIdx.x * 128;
    const int m0 = blockIdx.y * 128;

    int tid  = threadIdx.x;
    int wid  = tid >> 5;
    int lane = tid & 31;
    int grp  = lane >> 2;
    int tig  = lane & 3;
    int wm   = (wid & 1) * 64;
    int wn   = (wid >> 1) * 32;

    if (tid < 128) bsh[tid] = bias ? bias[n0 + tid] : 0.f;

    float acc[4][4][4];
    #pragma unroll
    for (int i = 0; i < 4; i++)
        #pragma unroll
        for (int j = 0; j < 4; j++)
            #pragma unroll
            for (int r = 0; r < 4; r++) acc[i][j][r] = 0.f;

    for (int k0 = 0; k0 < 256; k0 += 32) {
        #pragma unroll
        for (int t = 0; t < 4; t++) {
            int i   = tid + t * 256;
            int row = i >> 3;
            int q   = (i & 7) * 4;
            float4 v = *(const float4*)(A + (size_t)(m0 + row) * 256 + k0 + q);
            uint4 u;
            u.x = f2tf32(v.x); u.y = f2tf32(v.y);
            u.z = f2tf32(v.z); u.w = f2tf32(v.w);
            *(uint4*)(As + row * AS_STRIDE + q) = u;
        }
        #pragma unroll
        for (int t = 0; t < 4; t++) {
            int i = tid + t * 256;
            int k = i >> 5;
            int q = (i & 31) * 4;
            float4 v = *(const float4*)(Wm + (size_t)(k0 + k) * 256 + n0 + q);
            uint4 u;
            u.x = f2tf32(v.x); u.y = f2tf32(v.y);
            u.z = f2tf32(v.z); u.w = f2tf32(v.w);
            *(uint4*)(Bs + k * BS_STRIDE + q) = u;
        }
        __syncthreads();

        #pragma unroll
        for (int ks = 0; ks < 4; ks++) {
            int kk = ks * 8;
            uint32_t af[4][4], bf[4][2];
            #pragma unroll
            for (int mt = 0; mt < 4; mt++) {
                int r = wm + mt * 16 + grp;
                af[mt][0] = As[r * AS_STRIDE + kk + tig];
                af[mt][1] = As[(r + 8) * AS_STRIDE + kk + tig];
                af[mt][2] = As[r * AS_STRIDE + kk + tig + 4];
                af[mt][3] = As[(r + 8) * AS_STRIDE + kk + tig + 4];
            }
            #pragma unroll
            for (int nt = 0; nt < 4; nt++) {
                int c = wn + nt * 8 + grp;
                bf[nt][0] = Bs[(kk + tig) * BS_STRIDE + c];
                bf[nt][1] = Bs[(kk + tig + 4) * BS_STRIDE + c];
            }
            #pragma unroll
            for (int mt = 0; mt < 4; mt++)
                #pragma unroll
                for (int nt = 0; nt < 4; nt++)
                    mma_tf32(acc[mt][nt], af[mt], bf[nt][0], bf[nt][1]);
        }
        __syncthreads();
    }

    #pragma unroll
    for (int mt = 0; mt < 4; mt++) {
        #pragma unroll
        for (int nt = 0; nt < 4; nt++) {
            int cc = wn + nt * 8 + tig * 2;
            float b0 = bsh[cc], b1 = bsh[cc + 1];
            size_t r0 = (size_t)(m0 + wm + mt * 16 + grp) * 256 + n0 + cc;
            size_t r1 = r0 + 8 * 256;
            float2 v0 = {acc[mt][nt][0] + b0, acc[mt][nt][1] + b1};
            float2 v1 = {acc[mt][nt][2] + b0, acc[mt][nt][3] + b1};
            if (roundC) {
                v0.x = __uint_as_float(f2tf32(v0.x));
                v0.y = __uint_as_float(f2tf32(v0.y));
                v1.x = __uint_as_float(f2tf32(v1.x));
                v1.y = __uint_as_float(f2tf32(v1.y));
            }
            *(float2*)(C + r0) = v0;
            *(float2*)(C + r1) = v1;
        }
    }
}

// ---------------- aggregation GEMM with cp.async double buffer ----------------
// out[z][b] = A @ xw[z][b] + bias.  A and xw are pre-rounded tf32 -> raw copy.
#define AGG_ABUF (128 * AS_STRIDE)
#define AGG_BBUF (32 * BS_STRIDE)
#define AGG_SMEM ((2 * AGG_ABUF + 2 * AGG_BBUF + 128) * 4)

__global__ __launch_bounds__(256) void k_agg_gemm(
    const float* __restrict__ xq, const float* __restrict__ xk,
    const float* __restrict__ xv,
    const float* __restrict__ bq, const float* __restrict__ bk,
    const float* __restrict__ bv,
    float* __restrict__ oq, float* __restrict__ ok_, float* __restrict__ ov)
{
    extern __shared__ uint32_t dsm[];
    uint32_t* Asb = dsm;                          // 2 x AGG_ABUF
    uint32_t* Bsb = dsm + 2 * AGG_ABUF;           // 2 x AGG_BBUF
    float*    bsh = (float*)(dsm + 2 * AGG_ABUF + 2 * AGG_BBUF);

    int zz = blockIdx.z;
    int z  = zz >> 5;
    int b  = zz & 31;
    const float* X    = (z == 0) ? xq : (z == 1) ? xk : xv;
    const float* bias = (z == 0) ? bq : (z == 1) ? bk : bv;
    float*       O    = (z == 0) ? oq : (z == 1) ? ok_ : ov;
    const float* Xb = X + (size_t)b * NN * DD;
    float*       Cb = O + (size_t)b * NN * DD;

    const int n0 = blockIdx.x * 128;
    const int m0 = blockIdx.y * 128;

    int tid  = threadIdx.x;
    int wid  = tid >> 5;
    int lane = tid & 31;
    int grp  = lane >> 2;
    int tig  = lane & 3;
    int wm   = (wid & 1) * 64;
    int wn   = (wid >> 1) * 32;

    if (tid < 128) bsh[tid] = bias[n0 + tid];

    uint32_t sA = (uint32_t)__cvta_generic_to_shared(Asb);
    uint32_t sB = (uint32_t)__cvta_generic_to_shared(Bsb);

    // per-thread staging coordinates
    int arow = tid >> 1;                 // with t-offset: 4 tiles of 256
    // A: 4 x cp16: i = tid + t*256 -> row=i>>3, q=(i&7)*4
    // B: 4 x cp16: i = tid + t*256 -> k=i>>5,  q=(i&31)*4
    (void)arow;

    float acc[4][4][4];
    #pragma unroll
    for (int i = 0; i < 4; i++)
        #pragma unroll
        for (int j = 0; j < 4; j++)
            #pragma unroll
            for (int r = 0; r < 4; r++) acc[i][j][r] = 0.f;

    // prologue: stage chunk 0 into buffer 0
    #pragma unroll
    for (int t = 0; t < 4; t++) {
        int i = tid + t * 256;
        int row = i >> 3, q = (i & 7) * 4;
        cp16(sA + (row * AS_STRIDE + q) * 4, g_A + (size_t)(m0 + row) * NN + q);
    }
    #pragma unroll
    for (int t = 0; t < 4; t++) {
        int i = tid + t * 256;
        int k = i >> 5, q = (i & 31) * 4;
        cp16(sB + (k * BS_STRIDE + q) * 4, Xb + (size_t)k * 256 + n0 + q);
    }
    CP_COMMIT();

    for (int c = 0; c < 16; c++) {
        CP_WAIT0();
        __syncthreads();

        if (c + 1 < 16) {
            int k0  = (c + 1) * 32;
            int buf = (c + 1) & 1;
            uint32_t dA = sA + buf * AGG_ABUF * 4;
            uint32_t dB = sB + buf * AGG_BBUF * 4;
            #pragma unroll
            for (int t = 0; t < 4; t++) {
                int i = tid + t * 256;
                int row = i >> 3, q = (i & 7) * 4;
                cp16(dA + (row * AS_STRIDE + q) * 4,
                     g_A + (size_t)(m0 + row) * NN + k0 + q);
            }
            #pragma unroll
            for (int t = 0; t < 4; t++) {
                int i = tid + t * 256;
                int k = i >> 5, q = (i & 31) * 4;
                cp16(dB + (k * BS_STRIDE + q) * 4,
                     Xb + (size_t)(k0 + k) * 256 + n0 + q);
            }
            CP_COMMIT();
        }

        const uint32_t* As = Asb + (c & 1) * AGG_ABUF;
        const uint32_t* Bs = Bsb + (c & 1) * AGG_BBUF;

        #pragma unroll
        for (int ks = 0; ks < 4; ks++) {
            int kk = ks * 8;
            uint32_t af[4][4], bf[4][2];
            #pragma unroll
            for (int mt = 0; mt < 4; mt++) {
                int r = wm + mt * 16 + grp;
                af[mt][0] = As[r * AS_STRIDE + kk + tig];
                af[mt][1] = As[(r + 8) * AS_STRIDE + kk + tig];
                af[mt][2] = As[r * AS_STRIDE + kk + tig + 4];
                af[mt][3] = As[(r + 8) * AS_STRIDE + kk + tig + 4];
            }
            #pragma unroll
            for (int nt = 0; nt < 4; nt++) {
                int cc = wn + nt * 8 + grp;
                bf[nt][0] = Bs[(kk + tig) * BS_STRIDE + cc];
                bf[nt][1] = Bs[(kk + tig + 4) * BS_STRIDE + cc];
            }
            #pragma unroll
            for (int mt = 0; mt < 4; mt++)
                #pragma unroll
                for (int nt = 0; nt < 4; nt++)
                    mma_tf32(acc[mt][nt], af[mt], bf[nt][0], bf[nt][1]);
        }
        __syncthreads();
    }

    #pragma unroll
    for (int mt = 0; mt < 4; mt++) {
        #pragma unroll
        for (int nt = 0; nt < 4; nt++) {
            int cc = wn + nt * 8 + tig * 2;
            float b0 = bsh[cc], b1 = bsh[cc + 1];
            size_t r0 = (size_t)(m0 + wm + mt * 16 + grp) * 256 + n0 + cc;
            size_t r1 = r0 + 8 * 256;
            float2 v0 = {acc[mt][nt][0] + b0, acc[mt][nt][1] + b1};
            float2 v1 = {acc[mt][nt][2] + b0, acc[mt][nt][3] + b1};
            *(float2*)(Cb + r0) = v0;
            *(float2*)(Cb + r1) = v1;
        }
    }
}

// ---------------- flash attention on tf32 mma.sync (Round-7 proven) -----------
#define KV_ST 36
#define P_ST  68
#define ATT_SMEM ((64 * KV_ST * 2 + 8 * 16 * P_ST) * 4)

__global__ __launch_bounds__(256, 2) void k_attn(
    const float* __restrict__ Q, const float* __restrict__ K,
    const float* __restrict__ V, float* __restrict__ out)
{
    extern __shared__ float sm[];
    uint32_t* Ks = (uint32_t*)sm;
    uint32_t* Vs = Ks + 64 * KV_ST;
    uint32_t* Ps = Vs + 64 * KV_ST;

    int h   = blockIdx.y;
    int b   = blockIdx.z;
    int tid = threadIdx.x;
    int wid = tid >> 5, lane = tid & 31;
    int grp = lane >> 2, tig = lane & 3;
    int qw  = blockIdx.x * 128 + wid * 16;
    uint32_t* Pw = Ps + wid * 16 * P_ST;

    const float* Qb = Q + (size_t)b * NN * DD + h * HDIM;
    const float* Kb = K + (size_t)b * NN * DD + h * HDIM;
    const float* Vb = V + (size_t)b * NN * DD + h * HDIM;

    const float escale = 0.17677669529663687f;

    uint32_t qa[4][4];
    #pragma unroll
    for (int kf = 0; kf < 4; kf++) {
        int cl = kf * 8 + tig;
        qa[kf][0] = f2tf32(Qb[(size_t)(qw + grp) * DD + cl] * escale);
        qa[kf][1] = f2tf32(Qb[(size_t)(qw + grp + 8) * DD + cl] * escale);
        qa[kf][2] = f2tf32(Qb[(size_t)(qw + grp) * DD + cl + 4] * escale);
        qa[kf][3] = f2tf32(Qb[(size_t)(qw + grp + 8) * DD + cl + 4] * escale);
    }

    float m0 = -3.4e38f, m1 = -3.4e38f, l0 = 0.f, l1 = 0.f;
    float oacc[4][4];
    #pragma unroll
    for (int nt = 0; nt < 4; nt++)
        #pragma unroll
        for (int r = 0; r < 4; r++) oacc[nt][r] = 0.f;

    const uint32_t* bm0 = g_bmask + (size_t)(qw + grp) * 16;
    const uint32_t* bm1 = g_bmask + (size_t)(qw + grp + 8) * 16;

    for (int c0 = 0; c0 < NN; c0 += 64) {
        __syncthreads();
        #pragma unroll
        for (int t = 0; t < 2; t++) {
            int i = tid + t * 256;
            int r = i >> 3, f = (i & 7) * 4;
            float4 kv = *(const float4*)(Kb + (size_t)(c0 + r) * DD + f);
            float4 vv = *(const float4*)(Vb + (size_t)(c0 + r) * DD + f);
            uint4 ku, vu;
            ku.x = f2tf32(kv.x); ku.y = f2tf32(kv.y);
            ku.z = f2tf32(kv.z); ku.w = f2tf32(kv.w);
            vu.x = f2tf32(vv.x); vu.y = f2tf32(vv.y);
            vu.z = f2tf32(vv.z); vu.w = f2tf32(vv.w);
            *(uint4*)(Ks + r * KV_ST + f) = ku;
            *(uint4*)(Vs + r * KV_ST + f) = vu;
        }
        __syncthreads();

        float sacc[8][4];
        #pragma unroll
        for (int nt = 0; nt < 8; nt++)
            #pragma unroll
            for (int r = 0; r < 4; r++) sacc[nt][r] = 0.f;
        #pragma unroll
        for (int nt = 0; nt < 8; nt++)
            #pragma unroll
            for (int kf = 0; kf < 4; kf++) {
                uint32_t b0v = Ks[(nt * 8 + grp) * KV_ST + kf * 8 + tig];
                uint32_t b1v = Ks[(nt * 8 + grp) * KV_ST + kf * 8 + tig + 4];
                mma_tf32(sacc[nt], qa[kf], b0v, b1v);
            }

        uint32_t wa0 = bm0[c0 >> 5], wa1 = bm0[(c0 >> 5) + 1];
        uint32_t wb0 = bm1[c0 >> 5], wb1 = bm1[(c0 >> 5) + 1];
        float cm0 = -3.4e38f, cm1 = -3.4e38f;
        #pragma unroll
        for (int nt = 0; nt < 8; nt++) {
            int j  = nt * 8 + 2 * tig;
            uint32_t wa = (j < 32) ? wa0 : wa1;
            uint32_t wb = (j < 32) ? wb0 : wb1;
            int sh = j & 31;
            if (!((wa >> sh) & 1))        sacc[nt][0] = -1e10f;
            if (!((wa >> (sh + 1)) & 1))  sacc[nt][1] = -1e10f;
            if (!((wb >> sh) & 1))        sacc[nt][2] = -1e10f;
            if (!((wb >> (sh + 1)) & 1))  sacc[nt][3] = -1e10f;
            cm0 = fmaxf(cm0, fmaxf(sacc[nt][0], sacc[nt][1]));
            cm1 = fmaxf(cm1, fmaxf(sacc[nt][2], sacc[nt][3]));
        }
        cm0 = fmaxf(cm0, __shfl_xor_sync(0xffffffffu, cm0, 1));
        cm0 = fmaxf(cm0, __shfl_xor_sync(0xffffffffu, cm0, 2));
        cm1 = fmaxf(cm1, __shfl_xor_sync(0xffffffffu, cm1, 1));
        cm1 = fmaxf(cm1, __shfl_xor_sync(0xffffffffu, cm1, 2));

        float nm0 = fmaxf(m0, cm0), nm1 = fmaxf(m1, cm1);
        float f0 = __expf(m0 - nm0), f1 = __expf(m1 - nm1);
        l0 *= f0; l1 *= f1;
        #pragma unroll
        for (int nt = 0; nt < 4; nt++) {
            oacc[nt][0] *= f0; oacc[nt][1] *= f0;
            oacc[nt][2] *= f1; oacc[nt][3] *= f1;
        }
        m0 = nm0; m1 = nm1;

        #pragma unroll
        for (int nt = 0; nt < 8; nt++) {
            float p0 = __expf(sacc[nt][0] - nm0);
            float p1 = __expf(sacc[nt][1] - nm0);
            float p2 = __expf(sacc[nt][2] - nm1);
            float p3 = __expf(sacc[nt][3] - nm1);
            l0 += p0 + p1; l1 += p2 + p3;
            uint2 u0, u1;
            u0.x = f2tf32(p0); u0.y = f2tf32(p1);
            u1.x = f2tf32(p2); u1.y = f2tf32(p3);
            *(uint2*)(Pw + grp * P_ST + nt * 8 + 2 * tig) = u0;
            *(uint2*)(Pw + (grp + 8) * P_ST + nt * 8 + 2 * tig) = u1;
        }
        __syncwarp();

        #pragma unroll
        for (int kb = 0; kb < 8; kb++) {
            uint32_t pa[4];
            pa[0] = Pw[grp * P_ST + kb * 8 + tig];
            pa[1] = Pw[(grp + 8) * P_ST + kb * 8 + tig];
            pa[2] = Pw[grp * P_ST + kb * 8 + tig + 4];
            pa[3] = Pw[(grp + 8) * P_ST + kb * 8 + tig + 4];
            #pragma unroll
            for (int nt = 0; nt < 4; nt++) {
                uint32_t b0v = Vs[(kb * 8 + tig) * KV_ST + nt * 8 + grp];
                uint32_t b1v = Vs[(kb * 8 + tig + 4) * KV_ST + nt * 8 + grp];
                mma_tf32(oacc[nt], pa, b0v, b1v);
            }
        }
        __syncwarp();
    }

    l0 += __shfl_xor_sync(0xffffffffu, l0, 1);
    l0 += __shfl_xor_sync(0xffffffffu, l0, 2);
    l1 += __shfl_xor_sync(0xffffffffu, l1, 1);
    l1 += __shfl_xor_sync(0xffffffffu, l1, 2);
    float inv0 = 1.f / l0, inv1 = 1.f / l1;

    float* o0 = out + ((size_t)b * NN + qw + grp) * DD + h * HDIM;
    float* o1 = out + ((size_t)b * NN + qw + grp + 8) * DD + h * HDIM;
    #pragma unroll
    for (int nt = 0; nt < 4; nt++) {
        int cl = nt * 8 + 2 * tig;
        float2 v0 = {oacc[nt][0] * inv0, oacc[nt][1] * inv0};
        float2 v1 = {oacc[nt][2] * inv1, oacc[nt][3] * inv1};
        *(float2*)(o0 + cl) = v0;
        *(float2*)(o1 + cl) = v1;
    }
}

// ---------------- launch ------------------------------------------------------
extern "C" void kernel_launch(void* const* d_in, const int* in_sizes, int n_in,
                              void* d_out, int out_size) {
    const float* query = (const float*)d_in[0];
    const float* key   = (const float*)d_in[1];
    const float* value = (const float*)d_in[2];
    const int*   edge  = (const int*)d_in[3];
    const int*   mask  = (const int*)d_in[4];
    const float* Wq = (const float*)d_in[5];
    const float* bq = (const float*)d_in[6];
    const float* Wk = (const float*)d_in[7];
    const float* bk = (const float*)d_in[8];
    const float* Wv = (const float*)d_in[9];
    const float* bv = (const float*)d_in[10];
    const float* Wo = (const float*)d_in[11];
    const float* bo = (const float*)d_in[12];
    float* out = (float*)d_out;

    float *xwq, *xwk, *xwv, *Qp, *Kp, *Vp, *att;
    cudaGetSymbolAddress((void**)&xwq, g_xwq);
    cudaGetSymbolAddress((void**)&xwk, g_xwk);
    cudaGetSymbolAddress((void**)&xwv, g_xwv);
    cudaGetSymbolAddress((void**)&Qp,  g_Q);
    cudaGetSymbolAddress((void**)&Kp,  g_K);
    cudaGetSymbolAddress((void**)&Vp,  g_V);
    cudaGetSymbolAddress((void**)&att, g_att);

    cudaFuncSetAttribute(k_attn, cudaFuncAttributeMaxDynamicSharedMemorySize,
                         ATT_SMEM);
    cudaFuncSetAttribute(k_agg_gemm, cudaFuncAttributeMaxDynamicSharedMemorySize,
                         AGG_SMEM);

    // 1: graph prep + dense adjacency (tf32-rounded)
    k_graph<<<1, NN>>>(edge);
    // 2: mask packing
    k_pack<<<32, 256>>>(mask);

    // 3: fused QKV projection (outputs tf32-rounded for raw-copy staging)
    k_gemm_mma<<<dim3(2, 128, 3), 256>>>(query, key, value,
                                         Wq, Wk, Wv,
                                         xwq, xwk, xwv, nullptr, 1);

    // 4: aggregation GEMM, cp.async double-buffered  (<- ncu capture slot)
    k_agg_gemm<<<dim3(2, 4, 96), 256, AGG_SMEM>>>(xwq, xwk, xwv,
                                                  bq, bk, bv, Qp, Kp, Vp);

    // 5: flash attention (tf32 mma)
    k_attn<<<dim3(4, HH, BB), 256, ATT_SMEM>>>(Qp, Kp, Vp, att);

    // 6: output projection (+bias, full fp32 epilogue) into d_out
    k_gemm_mma<<<dim3(2, 128, 1), 256>>>(att, att, att,
                                         Wo, Wo, Wo,
                                         out, out, out, bo, 0);
}

// round 10
// speedup vs baseline: 1.7406x; 1.7406x over previous
#include <cuda_runtime.h>
#include <cstdint>

#define BB   32
#define NN   512
#define DD   256
#define HH   8
#define HDIM 32
#define EE   16384
#define ETOT (EE + NN)

// ---------------- scratch (static device globals; no allocation) -------------
__device__ float    g_xwq[BB * NN * DD];
__device__ float    g_xwk[BB * NN * DD];
__device__ float    g_xwv[BB * NN * DD];
__device__ float    g_Q  [BB * NN * DD];
__device__ float    g_K  [BB * NN * DD];
__device__ float    g_V  [BB * NN * DD];
__device__ float    g_att[BB * NN * DD];
__device__ int      g_rowptr[NN + 1];
__device__ int2     g_edge[ETOT];          // (src, norm-as-int)
__device__ uint32_t g_bmask[NN * 16];      // packed mask bits
__device__ float    g_A[NN * NN];          // dense normalized adjacency (tf32-rounded)

// ---------------- helpers -----------------------------------------------------
__device__ __forceinline__ uint32_t f2tf32(float f) {
    uint32_t r;
    asm("cvt.rna.tf32.f32 %0, %1;" : "=r"(r) : "f"(f));
    return r;
}
__device__ __forceinline__ void mma_tf32(float* c, const uint32_t* a,
                                         uint32_t b0, uint32_t b1) {
    asm volatile(
        "mma.sync.aligned.m16n8k8.row.col.f32.tf32.tf32.f32 "
        "{%0,%1,%2,%3}, {%4,%5,%6,%7}, {%8,%9}, {%0,%1,%2,%3};"
        : "+f"(c[0]), "+f"(c[1]), "+f"(c[2]), "+f"(c[3])
        : "r"(a[0]), "r"(a[1]), "r"(a[2]), "r"(a[3]), "r"(b0), "r"(b1));
}
__device__ __forceinline__ void cp16(uint32_t saddr, const void* g) {
    asm volatile("cp.async.ca.shared.global [%0], [%1], 16;"
                 :: "r"(saddr), "l"(g) : "memory");
}
#define CP_COMMIT() asm volatile("cp.async.commit_group;" ::: "memory")
#define CP_WAIT0()  asm volatile("cp.async.wait_group 0;" ::: "memory")

// ---------------- fused single-CTA graph prep + dense A (tf32) ----------------
__global__ __launch_bounds__(NN) void k_graph(const int* __restrict__ edge) {
    __shared__ int sdeg[NN];
    __shared__ int scnt[NN];
    __shared__ int srow[NN];
    __shared__ int ss[NN];
    __shared__ int se64;
    int t = threadIdx.x;

    if (t == 0) {
        int nz = 0;
        for (int i = 0; i < 64; i++) nz += (edge[2 * i + 1] != 0);
        se64 = (nz == 0) ? 1 : 0;
    }
    sdeg[t] = 0;
    scnt[t] = 0;
    __syncthreads();
    int e64 = se64;

    for (int e = t; e < ETOT; e += NN) {
        int dst = (e < EE) ? (e64 ? edge[2 * (EE + e)] : edge[EE + e]) : (e - EE);
        if (dst >= 0 && dst < NN) atomicAdd(&sdeg[dst], 1);
    }
    __syncthreads();

    ss[t] = sdeg[t];
    __syncthreads();
    for (int off = 1; off < NN; off <<= 1) {
        int v = (t >= off) ? ss[t - off] : 0;
        __syncthreads();
        ss[t] += v;
        __syncthreads();
    }
    srow[t] = ss[t] - sdeg[t];
    g_rowptr[t + 1] = ss[t];
    if (t == 0) g_rowptr[0] = 0;
    __syncthreads();

    for (int e = t; e < ETOT; e += NN) {
        int s, d;
        if (e < EE) {
            s = e64 ? edge[2 * e] : edge[e];
            d = e64 ? edge[2 * (EE + e)] : edge[EE + e];
        } else {
            s = e - EE; d = e - EE;
        }
        if (s < 0 || s >= NN || d < 0 || d >= NN) continue;
        float nm = rsqrtf((float)sdeg[s]) * rsqrtf((float)sdeg[d]);
        int pos = srow[d] + atomicAdd(&scnt[d], 1);
        g_edge[pos] = make_int2(s, __float_as_int(nm));
    }
    __syncthreads();

    // phase 1: coalesced zero of dense A (thread-linear float4)
    {
        float4* a4 = (float4*)g_A;
        const int total4 = NN * NN / 4;           // 65536
        for (int i = t; i < total4; i += NN)
            a4[i] = make_float4(0.f, 0.f, 0.f, 0.f);
    }
    __syncthreads();

    // phase 2: per-row serial edge fill (deterministic; duplicates accumulate)
    {
        float* arow = g_A + (size_t)t * NN;
        for (int i = srow[t]; i < ss[t]; i++) {
            int2 e = g_edge[i];
            arow[e.x] += __int_as_float(e.y);
        }
    }
    __syncthreads();

    // phase 3: coalesced tf32 rounding pass (thread-linear float4)
    {
        float4* a4 = (float4*)g_A;
        const int total4 = NN * NN / 4;
        for (int i = t; i < total4; i += NN) {
            float4 v = a4[i];
            v.x = __uint_as_float(f2tf32(v.x));
            v.y = __uint_as_float(f2tf32(v.y));
            v.z = __uint_as_float(f2tf32(v.z));
            v.w = __uint_as_float(f2tf32(v.w));
            a4[i] = v;
        }
    }
}

// ---------------- mask bit-packing --------------------------------------------
__global__ void k_pack(const int* __restrict__ mask) {
    int idx = blockIdx.x * 256 + threadIdx.x;   // 8192 words
    int r  = idx >> 4;
    int wd = idx & 15;
    const int* mrow = mask + (size_t)r * NN + wd * 32;
    uint32_t bits = 0;
    #pragma unroll
    for (int j = 0; j < 32; j++) bits |= (mrow[j] ? 1u : 0u) << j;
    g_bmask[idx] = bits;
}

// ---------------- tf32 mma.sync GEMM (projections / output) -------------------
#define AS_STRIDE 36
#define BS_STRIDE 132

__global__ __launch_bounds__(256) void k_gemm_mma(
    const float* __restrict__ a0p, const float* __restrict__ a1p,
    const float* __restrict__ a2p,
    const float* __restrict__ w0, const float* __restrict__ w1,
    const float* __restrict__ w2,
    float* __restrict__ c0p, float* __restrict__ c1p, float* __restrict__ c2p,
    const float* __restrict__ bias, int roundC)
{
    __shared__ uint32_t As[128 * AS_STRIDE];
    __shared__ uint32_t Bs[32 * BS_STRIDE];
    __shared__ float    bsh[128];

    const int z = blockIdx.z;
    const float* A  = (z == 0) ? a0p : (z == 1) ? a1p : a2p;
    const float* Wm = (z == 0) ? w0  : (z == 1) ? w1  : w2;
    float*       C  = (z == 0) ? c0p : (z == 1) ? c1p : c2p;

    const int n0 = blockIdx.x * 128;
    const int m0 = blockIdx.y * 128;

    int tid  = threadIdx.x;
    int wid  = tid >> 5;
    int lane = tid & 31;
    int grp  = lane >> 2;
    int tig  = lane & 3;
    int wm   = (wid & 1) * 64;
    int wn   = (wid >> 1) * 32;

    if (tid < 128) bsh[tid] = bias ? bias[n0 + tid] : 0.f;

    float acc[4][4][4];
    #pragma unroll
    for (int i = 0; i < 4; i++)
        #pragma unroll
        for (int j = 0; j < 4; j++)
            #pragma unroll
            for (int r = 0; r < 4; r++) acc[i][j][r] = 0.f;

    for (int k0 = 0; k0 < 256; k0 += 32) {
        #pragma unroll
        for (int t = 0; t < 4; t++) {
            int i   = tid + t * 256;
            int row = i >> 3;
            int q   = (i & 7) * 4;
            float4 v = *(const float4*)(A + (size_t)(m0 + row) * 256 + k0 + q);
            uint4 u;
            u.x = f2tf32(v.x); u.y = f2tf32(v.y);
            u.z = f2tf32(v.z); u.w = f2tf32(v.w);
            *(uint4*)(As + row * AS_STRIDE + q) = u;
        }
        #pragma unroll
        for (int t = 0; t < 4; t++) {
            int i = tid + t * 256;
            int k = i >> 5;
            int q = (i & 31) * 4;
            float4 v = *(const float4*)(Wm + (size_t)(k0 + k) * 256 + n0 + q);
            uint4 u;
            u.x = f2tf32(v.x); u.y = f2tf32(v.y);
            u.z = f2tf32(v.z); u.w = f2tf32(v.w);
            *(uint4*)(Bs + k * BS_STRIDE + q) = u;
        }
        __syncthreads();

        #pragma unroll
        for (int ks = 0; ks < 4; ks++) {
            int kk = ks * 8;
            uint32_t af[4][4], bf[4][2];
            #pragma unroll
            for (int mt = 0; mt < 4; mt++) {
                int r = wm + mt * 16 + grp;
                af[mt][0] = As[r * AS_STRIDE + kk + tig];
                af[mt][1] = As[(r + 8) * AS_STRIDE + kk + tig];
                af[mt][2] = As[r * AS_STRIDE + kk + tig + 4];
                af[mt][3] = As[(r + 8) * AS_STRIDE + kk + tig + 4];
            }
            #pragma unroll
            for (int nt = 0; nt < 4; nt++) {
                int c = wn + nt * 8 + grp;
                bf[nt][0] = Bs[(kk + tig) * BS_STRIDE + c];
                bf[nt][1] = Bs[(kk + tig + 4) * BS_STRIDE + c];
            }
            #pragma unroll
            for (int mt = 0; mt < 4; mt++)
                #pragma unroll
                for (int nt = 0; nt < 4; nt++)
                    mma_tf32(acc[mt][nt], af[mt], bf[nt][0], bf[nt][1]);
        }
        __syncthreads();
    }

    #pragma unroll
    for (int mt = 0; mt < 4; mt++) {
        #pragma unroll
        for (int nt = 0; nt < 4; nt++) {
            int cc = wn + nt * 8 + tig * 2;
            float b0 = bsh[cc], b1 = bsh[cc + 1];
            size_t r0 = (size_t)(m0 + wm + mt * 16 + grp) * 256 + n0 + cc;
            size_t r1 = r0 + 8 * 256;
            float2 v0 = {acc[mt][nt][0] + b0, acc[mt][nt][1] + b1};
            float2 v1 = {acc[mt][nt][2] + b0, acc[mt][nt][3] + b1};
            if (roundC) {
                v0.x = __uint_as_float(f2tf32(v0.x));
                v0.y = __uint_as_float(f2tf32(v0.y));
                v1.x = __uint_as_float(f2tf32(v1.x));
                v1.y = __uint_as_float(f2tf32(v1.y));
            }
            *(float2*)(C + r0) = v0;
            *(float2*)(C + r1) = v1;
        }
    }
}

// ---------------- aggregation GEMM with cp.async double buffer ----------------
#define AGG_ABUF (128 * AS_STRIDE)
#define AGG_BBUF (32 * BS_STRIDE)
#define AGG_SMEM ((2 * AGG_ABUF + 2 * AGG_BBUF + 128) * 4)

__global__ __launch_bounds__(256) void k_agg_gemm(
    const float* __restrict__ xq, const float* __restrict__ xk,
    const float* __restrict__ xv,
    const float* __restrict__ bq, const float* __restrict__ bk,
    const float* __restrict__ bv,
    float* __restrict__ oq, float* __restrict__ ok_, float* __restrict__ ov)
{
    extern __shared__ uint32_t dsm[];
    uint32_t* Asb = dsm;
    uint32_t* Bsb = dsm + 2 * AGG_ABUF;
    float*    bsh = (float*)(dsm + 2 * AGG_ABUF + 2 * AGG_BBUF);

    int zz = blockIdx.z;
    int z  = zz >> 5;
    int b  = zz & 31;
    const float* X    = (z == 0) ? xq : (z == 1) ? xk : xv;
    const float* bias = (z == 0) ? bq : (z == 1) ? bk : bv;
    float*       O    = (z == 0) ? oq : (z == 1) ? ok_ : ov;
    const float* Xb = X + (size_t)b * NN * DD;
    float*       Cb = O + (size_t)b * NN * DD;

    const int n0 = blockIdx.x * 128;
    const int m0 = blockIdx.y * 128;

    int tid  = threadIdx.x;
    int wid  = tid >> 5;
    int lane = tid & 31;
    int grp  = lane >> 2;
    int tig  = lane & 3;
    int wm   = (wid & 1) * 64;
    int wn   = (wid >> 1) * 32;

    if (tid < 128) bsh[tid] = bias[n0 + tid];

    uint32_t sA = (uint32_t)__cvta_generic_to_shared(Asb);
    uint32_t sB = (uint32_t)__cvta_generic_to_shared(Bsb);

    float acc[4][4][4];
    #pragma unroll
    for (int i = 0; i < 4; i++)
        #pragma unroll
        for (int j = 0; j < 4; j++)
            #pragma unroll
            for (int r = 0; r < 4; r++) acc[i][j][r] = 0.f;

    #pragma unroll
    for (int t = 0; t < 4; t++) {
        int i = tid + t * 256;
        int row = i >> 3, q = (i & 7) * 4;
        cp16(sA + (row * AS_STRIDE + q) * 4, g_A + (size_t)(m0 + row) * NN + q);
    }
    #pragma unroll
    for (int t = 0; t < 4; t++) {
        int i = tid + t * 256;
        int k = i >> 5, q = (i & 31) * 4;
        cp16(sB + (k * BS_STRIDE + q) * 4, Xb + (size_t)k * 256 + n0 + q);
    }
    CP_COMMIT();

    for (int c = 0; c < 16; c++) {
        CP_WAIT0();
        __syncthreads();

        if (c + 1 < 16) {
            int k0  = (c + 1) * 32;
            int buf = (c + 1) & 1;
            uint32_t dA = sA + buf * AGG_ABUF * 4;
            uint32_t dB = sB + buf * AGG_BBUF * 4;
            #pragma unroll
            for (int t = 0; t < 4; t++) {
                int i = tid + t * 256;
                int row = i >> 3, q = (i & 7) * 4;
                cp16(dA + (row * AS_STRIDE + q) * 4,
                     g_A + (size_t)(m0 + row) * NN + k0 + q);
            }
            #pragma unroll
            for (int t = 0; t < 4; t++) {
                int i = tid + t * 256;
                int k = i >> 5, q = (i & 31) * 4;
                cp16(dB + (k * BS_STRIDE + q) * 4,
                     Xb + (size_t)(k0 + k) * 256 + n0 + q);
            }
            CP_COMMIT();
        }

        const uint32_t* As = Asb + (c & 1) * AGG_ABUF;
        const uint32_t* Bs = Bsb + (c & 1) * AGG_BBUF;

        #pragma unroll
        for (int ks = 0; ks < 4; ks++) {
            int kk = ks * 8;
            uint32_t af[4][4], bf[4][2];
            #pragma unroll
            for (int mt = 0; mt < 4; mt++) {
                int r = wm + mt * 16 + grp;
                af[mt][0] = As[r * AS_STRIDE + kk + tig];
                af[mt][1] = As[(r + 8) * AS_STRIDE + kk + tig];
                af[mt][2] = As[r * AS_STRIDE + kk + tig + 4];
                af[mt][3] = As[(r + 8) * AS_STRIDE + kk + tig + 4];
            }
            #pragma unroll
            for (int nt = 0; nt < 4; nt++) {
                int cc = wn + nt * 8 + grp;
                bf[nt][0] = Bs[(kk + tig) * BS_STRIDE + cc];
                bf[nt][1] = Bs[(kk + tig + 4) * BS_STRIDE + cc];
            }
            #pragma unroll
            for (int mt = 0; mt < 4; mt++)
                #pragma unroll
                for (int nt = 0; nt < 4; nt++)
                    mma_tf32(acc[mt][nt], af[mt], bf[nt][0], bf[nt][1]);
        }
        __syncthreads();
    }

    #pragma unroll
    for (int mt = 0; mt < 4; mt++) {
        #pragma unroll
        for (int nt = 0; nt < 4; nt++) {
            int cc = wn + nt * 8 + tig * 2;
            float b0 = bsh[cc], b1 = bsh[cc + 1];
            size_t r0 = (size_t)(m0 + wm + mt * 16 + grp) * 256 + n0 + cc;
            size_t r1 = r0 + 8 * 256;
            float2 v0 = {acc[mt][nt][0] + b0, acc[mt][nt][1] + b1};
            float2 v1 = {acc[mt][nt][2] + b0, acc[mt][nt][3] + b1};
            *(float2*)(Cb + r0) = v0;
            *(float2*)(Cb + r1) = v1;
        }
    }
}

// ---------------- flash attention on tf32 mma.sync ----------------------------
#define KV_ST 36
#define P_ST  68
#define ATT_SMEM ((64 * KV_ST * 2 + 8 * 16 * P_ST) * 4)

__global__ __launch_bounds__(256, 2) void k_attn(
    const float* __restrict__ Q, const float* __restrict__ K,
    const float* __restrict__ V, float* __restrict__ out)
{
    extern __shared__ float sm[];
    uint32_t* Ks = (uint32_t*)sm;
    uint32_t* Vs = Ks + 64 * KV_ST;
    uint32_t* Ps = Vs + 64 * KV_ST;

    int h   = blockIdx.y;
    int b   = blockIdx.z;
    int tid = threadIdx.x;
    int wid = tid >> 5, lane = tid & 31;
    int grp = lane >> 2, tig = lane & 3;
    int qw  = blockIdx.x * 128 + wid * 16;
    uint32_t* Pw = Ps + wid * 16 * P_ST;

    const float* Qb = Q + (size_t)b * NN * DD + h * HDIM;
    const float* Kb = K + (size_t)b * NN * DD + h * HDIM;
    const float* Vb = V + (size_t)b * NN * DD + h * HDIM;

    const float escale = 0.17677669529663687f;

    uint32_t qa[4][4];
    #pragma unroll
    for (int kf = 0; kf < 4; kf++) {
        int cl = kf * 8 + tig;
        qa[kf][0] = f2tf32(Qb[(size_t)(qw + grp) * DD + cl] * escale);
        qa[kf][1] = f2tf32(Qb[(size_t)(qw + grp + 8) * DD + cl] * escale);
        qa[kf][2] = f2tf32(Qb[(size_t)(qw + grp) * DD + cl + 4] * escale);
        qa[kf][3] = f2tf32(Qb[(size_t)(qw + grp + 8) * DD + cl + 4] * escale);
    }

    float m0 = -3.4e38f, m1 = -3.4e38f, l0 = 0.f, l1 = 0.f;
    float oacc[4][4];
    #pragma unroll
    for (int nt = 0; nt < 4; nt++)
        #pragma unroll
        for (int r = 0; r < 4; r++) oacc[nt][r] = 0.f;

    const uint32_t* bm0 = g_bmask + (size_t)(qw + grp) * 16;
    const uint32_t* bm1 = g_bmask + (size_t)(qw + grp + 8) * 16;

    for (int c0 = 0; c0 < NN; c0 += 64) {
        __syncthreads();
        #pragma unroll
        for (int t = 0; t < 2; t++) {
            int i = tid + t * 256;
            int r = i >> 3, f = (i & 7) * 4;
            float4 kv = *(const float4*)(Kb + (size_t)(c0 + r) * DD + f);
            float4 vv = *(const float4*)(Vb + (size_t)(c0 + r) * DD + f);
            uint4 ku, vu;
            ku.x = f2tf32(kv.x); ku.y = f2tf32(kv.y);
            ku.z = f2tf32(kv.z); ku.w = f2tf32(kv.w);
            vu.x = f2tf32(vv.x); vu.y = f2tf32(vv.y);
            vu.z = f2tf32(vv.z); vu.w = f2tf32(vv.w);
            *(uint4*)(Ks + r * KV_ST + f) = ku;
            *(uint4*)(Vs + r * KV_ST + f) = vu;
        }
        __syncthreads();

        float sacc[8][4];
        #pragma unroll
        for (int nt = 0; nt < 8; nt++)
            #pragma unroll
            for (int r = 0; r < 4; r++) sacc[nt][r] = 0.f;
        #pragma unroll
        for (int nt = 0; nt < 8; nt++)
            #pragma unroll
            for (int kf = 0; kf < 4; kf++) {
                uint32_t b0v = Ks[(nt * 8 + grp) * KV_ST + kf * 8 + tig];
                uint32_t b1v = Ks[(nt * 8 + grp) * KV_ST + kf * 8 + tig + 4];
                mma_tf32(sacc[nt], qa[kf], b0v, b1v);
            }

        uint32_t wa0 = bm0[c0 >> 5], wa1 = bm0[(c0 >> 5) + 1];
        uint32_t wb0 = bm1[c0 >> 5], wb1 = bm1[(c0 >> 5) + 1];
        float cm0 = -3.4e38f, cm1 = -3.4e38f;
        #pragma unroll
        for (int nt = 0; nt < 8; nt++) {
            int j  = nt * 8 + 2 * tig;
            uint32_t wa = (j < 32) ? wa0 : wa1;
            uint32_t wb = (j < 32) ? wb0 : wb1;
            int sh = j & 31;
            if (!((wa >> sh) & 1))        sacc[nt][0] = -1e10f;
            if (!((wa >> (sh + 1)) & 1))  sacc[nt][1] = -1e10f;
            if (!((wb >> sh) & 1))        sacc[nt][2] = -1e10f;
            if (!((wb >> (sh + 1)) & 1))  sacc[nt][3] = -1e10f;
            cm0 = fmaxf(cm0, fmaxf(sacc[nt][0], sacc[nt][1]));
            cm1 = fmaxf(cm1, fmaxf(sacc[nt][2], sacc[nt][3]));
        }
        cm0 = fmaxf(cm0, __shfl_xor_sync(0xffffffffu, cm0, 1));
        cm0 = fmaxf(cm0, __shfl_xor_sync(0xffffffffu, cm0, 2));
        cm1 = fmaxf(cm1, __shfl_xor_sync(0xffffffffu, cm1, 1));
        cm1 = fmaxf(cm1, __shfl_xor_sync(0xffffffffu, cm1, 2));

        float nm0 = fmaxf(m0, cm0), nm1 = fmaxf(m1, cm1);
        float f0 = __expf(m0 - nm0), f1 = __expf(m1 - nm1);
        l0 *= f0; l1 *= f1;
        #pragma unroll
        for (int nt = 0; nt < 4; nt++) {
            oacc[nt][0] *= f0; oacc[nt][1] *= f0;
            oacc[nt][2] *= f1; oacc[nt][3] *= f1;
        }
        m0 = nm0; m1 = nm1;

        #pragma unroll
        for (int nt = 0; nt < 8; nt++) {
            float p0 = __expf(sacc[nt][0] - nm0);
            float p1 = __expf(sacc[nt][1] - nm0);
            float p2 = __expf(sacc[nt][2] - nm1);
            float p3 = __expf(sacc[nt][3] - nm1);
            l0 += p0 + p1; l1 += p2 + p3;
            uint2 u0, u1;
            u0.x = f2tf32(p0); u0.y = f2tf32(p1);
            u1.x = f2tf32(p2); u1.y = f2tf32(p3);
            *(uint2*)(Pw + grp * P_ST + nt * 8 + 2 * tig) = u0;
            *(uint2*)(Pw + (grp + 8) * P_ST + nt * 8 + 2 * tig) = u1;
        }
        __syncwarp();

        #pragma unroll
        for (int kb = 0; kb < 8; kb++) {
            uint32_t pa[4];
            pa[0] = Pw[grp * P_ST + kb * 8 + tig];
            pa[1] = Pw[(grp + 8) * P_ST + kb * 8 + tig];
            pa[2] = Pw[grp * P_ST + kb * 8 + tig + 4];
            pa[3] = Pw[(grp + 8) * P_ST + kb * 8 + tig + 4];
            #pragma unroll
            for (int nt = 0; nt < 4; nt++) {
                uint32_t b0v = Vs[(kb * 8 + tig) * KV_ST + nt * 8 + grp];
                uint32_t b1v = Vs[(kb * 8 + tig + 4) * KV_ST + nt * 8 + grp];
                mma_tf32(oacc[nt], pa, b0v, b1v);
            }
        }
        __syncwarp();
    }

    l0 += __shfl_xor_sync(0xffffffffu, l0, 1);
    l0 += __shfl_xor_sync(0xffffffffu, l0, 2);
    l1 += __shfl_xor_sync(0xffffffffu, l1, 1);
    l1 += __shfl_xor_sync(0xffffffffu, l1, 2);
    float inv0 = 1.f / l0, inv1 = 1.f / l1;

    float* o0 = out + ((size_t)b * NN + qw + grp) * DD + h * HDIM;
    float* o1 = out + ((size_t)b * NN + qw + grp + 8) * DD + h * HDIM;
    #pragma unroll
    for (int nt = 0; nt < 4; nt++) {
        int cl = nt * 8 + 2 * tig;
        float2 v0 = {oacc[nt][0] * inv0, oacc[nt][1] * inv0};
        float2 v1 = {oacc[nt][2] * inv1, oacc[nt][3] * inv1};
        *(float2*)(o0 + cl) = v0;
        *(float2*)(o1 + cl) = v1;
    }
}

// ---------------- launch ------------------------------------------------------
extern "C" void kernel_launch(void* const* d_in, const int* in_sizes, int n_in,
                              void* d_out, int out_size) {
    const float* query = (const float*)d_in[0];
    const float* key   = (const float*)d_in[1];
    const float* value = (const float*)d_in[2];
    const int*   edge  = (const int*)d_in[3];
    const int*   mask  = (const int*)d_in[4];
    const float* Wq = (const float*)d_in[5];
    const float* bq = (const float*)d_in[6];
    const float* Wk = (const float*)d_in[7];
    const float* bk = (const float*)d_in[8];
    const float* Wv = (const float*)d_in[9];
    const float* bv = (const float*)d_in[10];
    const float* Wo = (const float*)d_in[11];
    const float* bo = (const float*)d_in[12];
    float* out = (float*)d_out;

    float *xwq, *xwk, *xwv, *Qp, *Kp, *Vp, *att;
    cudaGetSymbolAddress((void**)&xwq, g_xwq);
    cudaGetSymbolAddress((void**)&xwk, g_xwk);
    cudaGetSymbolAddress((void**)&xwv, g_xwv);
    cudaGetSymbolAddress((void**)&Qp,  g_Q);
    cudaGetSymbolAddress((void**)&Kp,  g_K);
    cudaGetSymbolAddress((void**)&Vp,  g_V);
    cudaGetSymbolAddress((void**)&att, g_att);

    cudaFuncSetAttribute(k_attn, cudaFuncAttributeMaxDynamicSharedMemorySize,
                         ATT_SMEM);
    cudaFuncSetAttribute(k_agg_gemm, cudaFuncAttributeMaxDynamicSharedMemorySize,
                         AGG_SMEM);

    // 1: graph prep + dense adjacency (coalesced zero/round passes)
    k_graph<<<1, NN>>>(edge);
    // 2: mask packing
    k_pack<<<32, 256>>>(mask);

    // 3: fused QKV projection (outputs tf32-rounded for raw-copy staging)
    k_gemm_mma<<<dim3(2, 128, 3), 256>>>(query, key, value,
                                         Wq, Wk, Wv,
                                         xwq, xwk, xwv, nullptr, 1);

    // 4: aggregation GEMM, cp.async double-buffered  (<- ncu capture slot)
    k_agg_gemm<<<dim3(2, 4, 96), 256, AGG_SMEM>>>(xwq, xwk, xwv,
                                                  bq, bk, bv, Qp, Kp, Vp);

    // 5: flash attention (tf32 mma)
    k_attn<<<dim3(4, HH, BB), 256, ATT_SMEM>>>(Qp, Kp, Vp, att);

    // 6: output projection (+bias, full fp32 epilogue) into d_out
    k_gemm_mma<<<dim3(2, 128, 1), 256>>>(att, att, att,
                                         Wo, Wo, Wo,
                                         out, out, out, bo, 0);
}

// round 12
// speedup vs baseline: 1.9677x; 1.1305x over previous
#include <cuda_runtime.h>
#include <cstdint>

#define BB   32
#define NN   512
#define DD   256
#define HH   8
#define HDIM 32
#define EE   16384
#define ETOT (EE + NN)

// ---------------- scratch (static device globals; no allocation) -------------
__device__ float    g_xwq[BB * NN * DD];
__device__ float    g_xwk[BB * NN * DD];
__device__ float    g_xwv[BB * NN * DD];
__device__ float    g_Q  [BB * NN * DD];
__device__ float    g_K  [BB * NN * DD];
__device__ float    g_V  [BB * NN * DD];
__device__ float    g_att[BB * NN * DD];
__device__ int      g_rowptr[NN + 1];
__device__ int2     g_edge[ETOT];          // (src, norm-as-int)
__device__ uint32_t g_bmask[NN * 16];      // packed mask bits
__device__ float    g_A[NN * NN];          // dense normalized adjacency

// ---------------- helpers -----------------------------------------------------
__device__ __forceinline__ uint32_t f2tf32(float f) {
    uint32_t r;
    asm("cvt.rna.tf32.f32 %0, %1;" : "=r"(r) : "f"(f));
    return r;
}
__device__ __forceinline__ void mma_tf32(float* c, const uint32_t* a,
                                         uint32_t b0, uint32_t b1) {
    asm volatile(
        "mma.sync.aligned.m16n8k8.row.col.f32.tf32.tf32.f32 "
        "{%0,%1,%2,%3}, {%4,%5,%6,%7}, {%8,%9}, {%0,%1,%2,%3};"
        : "+f"(c[0]), "+f"(c[1]), "+f"(c[2]), "+f"(c[3])
        : "r"(a[0]), "r"(a[1]), "r"(a[2]), "r"(a[3]), "r"(b0), "r"(b1));
}
__device__ __forceinline__ void cp16(uint32_t saddr, const void* g) {
    asm volatile("cp.async.ca.shared.global [%0], [%1], 16;"
                 :: "r"(saddr), "l"(g) : "memory");
}
#define CP_COMMIT() asm volatile("cp.async.commit_group;" ::: "memory")
#define CP_WAIT0()  asm volatile("cp.async.wait_group 0;" ::: "memory")

// ---------------- fused single-CTA graph prep + dense A fill ------------------
__global__ __launch_bounds__(NN) void k_graph(const int* __restrict__ edge) {
    __shared__ int sdeg[NN];
    __shared__ int scnt[NN];
    __shared__ int srow[NN];
    __shared__ int ss[NN];
    __shared__ int se64;
    int t = threadIdx.x;

    if (t == 0) {
        int nz = 0;
        for (int i = 0; i < 64; i++) nz += (edge[2 * i + 1] != 0);
        se64 = (nz == 0) ? 1 : 0;
    }
    sdeg[t] = 0;
    scnt[t] = 0;
    __syncthreads();
    int e64 = se64;

    for (int e = t; e < ETOT; e += NN) {
        int dst = (e < EE) ? (e64 ? edge[2 * (EE + e)] : edge[EE + e]) : (e - EE);
        if (dst >= 0 && dst < NN) atomicAdd(&sdeg[dst], 1);
    }
    __syncthreads();

    ss[t] = sdeg[t];
    __syncthreads();
    for (int off = 1; off < NN; off <<= 1) {
        int v = (t >= off) ? ss[t - off] : 0;
        __syncthreads();
        ss[t] += v;
        __syncthreads();
    }
    srow[t] = ss[t] - sdeg[t];
    g_rowptr[t + 1] = ss[t];
    if (t == 0) g_rowptr[0] = 0;
    __syncthreads();

    for (int e = t; e < ETOT; e += NN) {
        int s, d;
        if (e < EE) {
            s = e64 ? edge[2 * e] : edge[e];
            d = e64 ? edge[2 * (EE + e)] : edge[EE + e];
        } else {
            s = e - EE; d = e - EE;
        }
        if (s < 0 || s >= NN || d < 0 || d >= NN) continue;
        float nm = rsqrtf((float)sdeg[s]) * rsqrtf((float)sdeg[d]);
        int pos = srow[d] + atomicAdd(&scnt[d], 1);
        g_edge[pos] = make_int2(s, __float_as_int(nm));
    }
    __syncthreads();

    // coalesced zero of dense A
    {
        float4* a4 = (float4*)g_A;
        for (int i = t; i < NN * NN / 4; i += NN)
            a4[i] = make_float4(0.f, 0.f, 0.f, 0.f);
    }
    __syncthreads();

    // per-row serial edge fill (deterministic; duplicates accumulate)
    {
        float* arow = g_A + (size_t)t * NN;
        for (int i = srow[t]; i < ss[t]; i++) {
            int2 e = g_edge[i];
            arow[e.x] += __int_as_float(e.y);
        }
    }
    // tf32 rounding of A happens in proj service CTAs (grid-wide, coalesced)
}

// ---------------- tf32 mma.sync GEMM + service slice (round A, pack mask) -----
#define AS_STRIDE 36
#define BS_STRIDE 132

__global__ __launch_bounds__(256) void k_gemm_mma(
    const float* __restrict__ a0p, const float* __restrict__ a1p,
    const float* __restrict__ a2p,
    const float* __restrict__ w0, const float* __restrict__ w1,
    const float* __restrict__ w2,
    float* __restrict__ c0p, float* __restrict__ c1p, float* __restrict__ c2p,
    const float* __restrict__ bias, const int* __restrict__ mask, int roundC)
{
    const int z = blockIdx.z;
    int tid = threadIdx.x;

    if (z == 3) {
        // service CTAs: round dense A to tf32 + pack mask bits
        int cta = blockIdx.x * 128 + blockIdx.y;    // 0..255
        int i4  = cta * 256 + tid;                  // 65536 float4s
        float4* a4 = (float4*)g_A;
        float4 v = a4[i4];
        v.x = __uint_as_float(f2tf32(v.x));
        v.y = __uint_as_float(f2tf32(v.y));
        v.z = __uint_as_float(f2tf32(v.z));
        v.w = __uint_as_float(f2tf32(v.w));
        a4[i4] = v;
        if (cta < 32 && mask) {
            int idx = cta * 256 + tid;              // 8192 words
            int r  = idx >> 4;
            int wd = idx & 15;
            const int* mrow = mask + (size_t)r * NN + wd * 32;
            uint32_t bits = 0;
            #pragma unroll
            for (int j = 0; j < 32; j++) bits |= (mrow[j] ? 1u : 0u) << j;
            g_bmask[idx] = bits;
        }
        return;
    }

    __shared__ uint32_t As[128 * AS_STRIDE];
    __shared__ uint32_t Bs[32 * BS_STRIDE];
    __shared__ float    bsh[128];

    const float* A  = (z == 0) ? a0p : (z == 1) ? a1p : a2p;
    const float* Wm = (z == 0) ? w0  : (z == 1) ? w1  : w2;
    float*       C  = (z == 0) ? c0p : (z == 1) ? c1p : c2p;

    const int n0 = blockIdx.x * 128;
    const int m0 = blockIdx.y * 128;

    int wid  = tid >> 5;
    int lane = tid & 31;
    int grp  = lane >> 2;
    int tig  = lane & 3;
    int wm   = (wid & 1) * 64;
    int wn   = (wid >> 1) * 32;

    if (tid < 128) bsh[tid] = bias ? bias[n0 + tid] : 0.f;

    float acc[4][4][4];
    #pragma unroll
    for (int i = 0; i < 4; i++)
        #pragma unroll
        for (int j = 0; j < 4; j++)
            #pragma unroll
            for (int r = 0; r < 4; r++) acc[i][j][r] = 0.f;

    for (int k0 = 0; k0 < 256; k0 += 32) {
        #pragma unroll
        for (int t = 0; t < 4; t++) {
            int i   = tid + t * 256;
            int row = i >> 3;
            int q   = (i & 7) * 4;
            float4 v = *(const float4*)(A + (size_t)(m0 + row) * 256 + k0 + q);
            uint4 u;
            u.x = f2tf32(v.x); u.y = f2tf32(v.y);
            u.z = f2tf32(v.z); u.w = f2tf32(v.w);
            *(uint4*)(As + row * AS_STRIDE + q) = u;
        }
        #pragma unroll
        for (int t = 0; t < 4; t++) {
            int i = tid + t * 256;
            int k = i >> 5;
            int q = (i & 31) * 4;
            float4 v = *(const float4*)(Wm + (size_t)(k0 + k) * 256 + n0 + q);
            uint4 u;
            u.x = f2tf32(v.x); u.y = f2tf32(v.y);
            u.z = f2tf32(v.z); u.w = f2tf32(v.w);
            *(uint4*)(Bs + k * BS_STRIDE + q) = u;
        }
        __syncthreads();

        #pragma unroll
        for (int ks = 0; ks < 4; ks++) {
            int kk = ks * 8;
            uint32_t af[4][4], bf[4][2];
            #pragma unroll
            for (int mt = 0; mt < 4; mt++) {
                int r = wm + mt * 16 + grp;
                af[mt][0] = As[r * AS_STRIDE + kk + tig];
                af[mt][1] = As[(r + 8) * AS_STRIDE + kk + tig];
                af[mt][2] = As[r * AS_STRIDE + kk + tig + 4];
                af[mt][3] = As[(r + 8) * AS_STRIDE + kk + tig + 4];
            }
            #pragma unroll
            for (int nt = 0; nt < 4; nt++) {
                int c = wn + nt * 8 + grp;
                bf[nt][0] = Bs[(kk + tig) * BS_STRIDE + c];
                bf[nt][1] = Bs[(kk + tig + 4) * BS_STRIDE + c];
            }
            #pragma unroll
            for (int mt = 0; mt < 4; mt++)
                #pragma unroll
                for (int nt = 0; nt < 4; nt++)
                    mma_tf32(acc[mt][nt], af[mt], bf[nt][0], bf[nt][1]);
        }
        __syncthreads();
    }

    #pragma unroll
    for (int mt = 0; mt < 4; mt++) {
        #pragma unroll
        for (int nt = 0; nt < 4; nt++) {
            int cc = wn + nt * 8 + tig * 2;
            float b0 = bsh[cc], b1 = bsh[cc + 1];
            size_t r0 = (size_t)(m0 + wm + mt * 16 + grp) * 256 + n0 + cc;
            size_t r1 = r0 + 8 * 256;
            float2 v0 = {acc[mt][nt][0] + b0, acc[mt][nt][1] + b1};
            float2 v1 = {acc[mt][nt][2] + b0, acc[mt][nt][3] + b1};
            if (roundC) {
                v0.x = __uint_as_float(f2tf32(v0.x));
                v0.y = __uint_as_float(f2tf32(v0.y));
                v1.x = __uint_as_float(f2tf32(v1.x));
                v1.y = __uint_as_float(f2tf32(v1.y));
            }
            *(float2*)(C + r0) = v0;
            *(float2*)(C + r1) = v1;
        }
    }
}

// ---------------- aggregation GEMM, cp.async 2-stage; outputs tf32-rounded ----
#define AGG_ABUF (128 * AS_STRIDE)
#define AGG_BBUF (32 * BS_STRIDE)
#define AGG_SMEM ((2 * AGG_ABUF + 2 * AGG_BBUF + 128) * 4)

__global__ __launch_bounds__(256) void k_agg_gemm(
    const float* __restrict__ xq, const float* __restrict__ xk,
    const float* __restrict__ xv,
    const float* __restrict__ bq, const float* __restrict__ bk,
    const float* __restrict__ bv,
    float* __restrict__ oq, float* __restrict__ ok_, float* __restrict__ ov)
{
    extern __shared__ uint32_t dsm[];
    uint32_t* Asb = dsm;
    uint32_t* Bsb = dsm + 2 * AGG_ABUF;
    float*    bsh = (float*)(dsm + 2 * AGG_ABUF + 2 * AGG_BBUF);

    int zz = blockIdx.z;
    int z  = zz >> 5;
    int b  = zz & 31;
    const float* X    = (z == 0) ? xq : (z == 1) ? xk : xv;
    const float* bias = (z == 0) ? bq : (z == 1) ? bk : bv;
    float*       O    = (z == 0) ? oq : (z == 1) ? ok_ : ov;
    const float* Xb = X + (size_t)b * NN * DD;
    float*       Cb = O + (size_t)b * NN * DD;

    const int n0 = blockIdx.x * 128;
    const int m0 = blockIdx.y * 128;

    int tid  = threadIdx.x;
    int wid  = tid >> 5;
    int lane = tid & 31;
    int grp  = lane >> 2;
    int tig  = lane & 3;
    int wm   = (wid & 1) * 64;
    int wn   = (wid >> 1) * 32;

    if (tid < 128) bsh[tid] = bias[n0 + tid];

    uint32_t sA = (uint32_t)__cvta_generic_to_shared(Asb);
    uint32_t sB = (uint32_t)__cvta_generic_to_shared(Bsb);

    float acc[4][4][4];
    #pragma unroll
    for (int i = 0; i < 4; i++)
        #pragma unroll
        for (int j = 0; j < 4; j++)
            #pragma unroll
            for (int r = 0; r < 4; r++) acc[i][j][r] = 0.f;

    #pragma unroll
    for (int t = 0; t < 4; t++) {
        int i = tid + t * 256;
        int row = i >> 3, q = (i & 7) * 4;
        cp16(sA + (row * AS_STRIDE + q) * 4, g_A + (size_t)(m0 + row) * NN + q);
    }
    #pragma unroll
    for (int t = 0; t < 4; t++) {
        int i = tid + t * 256;
        int k = i >> 5, q = (i & 31) * 4;
        cp16(sB + (k * BS_STRIDE + q) * 4, Xb + (size_t)k * 256 + n0 + q);
    }
    CP_COMMIT();

    for (int c = 0; c < 16; c++) {
        CP_WAIT0();
        __syncthreads();

        if (c + 1 < 16) {
            int k0  = (c + 1) * 32;
            int buf = (c + 1) & 1;
            uint32_t dA = sA + buf * AGG_ABUF * 4;
            uint32_t dB = sB + buf * AGG_BBUF * 4;
            #pragma unroll
            for (int t = 0; t < 4; t++) {
                int i = tid + t * 256;
                int row = i >> 3, q = (i & 7) * 4;
                cp16(dA + (row * AS_STRIDE + q) * 4,
                     g_A + (size_t)(m0 + row) * NN + k0 + q);
            }
            #pragma unroll
            for (int t = 0; t < 4; t++) {
                int i = tid + t * 256;
                int k = i >> 5, q = (i & 31) * 4;
                cp16(dB + (k * BS_STRIDE + q) * 4,
                     Xb + (size_t)(k0 + k) * 256 + n0 + q);
            }
            CP_COMMIT();
        }

        const uint32_t* As = Asb + (c & 1) * AGG_ABUF;
        const uint32_t* Bs = Bsb + (c & 1) * AGG_BBUF;

        #pragma unroll
        for (int ks = 0; ks < 4; ks++) {
            int kk = ks * 8;
            uint32_t af[4][4], bf[4][2];
            #pragma unroll
            for (int mt = 0; mt < 4; mt++) {
                int r = wm + mt * 16 + grp;
                af[mt][0] = As[r * AS_STRIDE + kk + tig];
                af[mt][1] = As[(r + 8) * AS_STRIDE + kk + tig];
                af[mt][2] = As[r * AS_STRIDE + kk + tig + 4];
                af[mt][3] = As[(r + 8) * AS_STRIDE + kk + tig + 4];
            }
            #pragma unroll
            for (int nt = 0; nt < 4; nt++) {
                int cc = wn + nt * 8 + grp;
                bf[nt][0] = Bs[(kk + tig) * BS_STRIDE + cc];
                bf[nt][1] = Bs[(kk + tig + 4) * BS_STRIDE + cc];
            }
            #pragma unroll
            for (int mt = 0; mt < 4; mt++)
                #pragma unroll
                for (int nt = 0; nt < 4; nt++)
                    mma_tf32(acc[mt][nt], af[mt], bf[nt][0], bf[nt][1]);
        }
        __syncthreads();
    }

    // epilogue: bias + tf32-round (outputs feed MMAs only -> numerically free)
    #pragma unroll
    for (int mt = 0; mt < 4; mt++) {
        #pragma unroll
        for (int nt = 0; nt < 4; nt++) {
            int cc = wn + nt * 8 + tig * 2;
            float b0 = bsh[cc], b1 = bsh[cc + 1];
            size_t r0 = (size_t)(m0 + wm + mt * 16 + grp) * 256 + n0 + cc;
            size_t r1 = r0 + 8 * 256;
            float2 v0, v1;
            v0.x = __uint_as_float(f2tf32(acc[mt][nt][0] + b0));
            v0.y = __uint_as_float(f2tf32(acc[mt][nt][1] + b1));
            v1.x = __uint_as_float(f2tf32(acc[mt][nt][2] + b0));
            v1.y = __uint_as_float(f2tf32(acc[mt][nt][3] + b1));
            *(float2*)(Cb + r0) = v0;
            *(float2*)(Cb + r1) = v1;
        }
    }
}

// ---------------- flash attention: cp.async KV pipeline + shuffle-P -----------
// Q/K/V are pre-rounded tf32. escale folded into exp argument.
#define KV_W  36
#define KVBUF (2 * 64 * KV_W)               // K tile + V tile (words)
#define ATT_SMEM (2 * KVBUF * 4)            // double buffered

__global__ __launch_bounds__(256, 2) void k_attn(
    const float* __restrict__ Q, const float* __restrict__ K,
    const float* __restrict__ V, float* __restrict__ out)
{
    extern __shared__ uint32_t sm[];

    int h   = blockIdx.y;
    int b   = blockIdx.z;
    int tid = threadIdx.x;
    int wid = tid >> 5, lane = tid & 31;
    int grp = lane >> 2, tig = lane & 3;
    int qw  = blockIdx.x * 128 + wid * 16;

    const float* Qb = Q + (size_t)b * NN * DD + h * HDIM;
    const float* Kb = K + (size_t)b * NN * DD + h * HDIM;
    const float* Vb = V + (size_t)b * NN * DD + h * HDIM;

    const float escale = 0.17677669529663687f;   // 1/sqrt(HD)

    // Q a-fragments: raw tf32 bit loads (pre-rounded, unscaled)
    uint32_t qa[4][4];
    #pragma unroll
    for (int kf = 0; kf < 4; kf++) {
        int cl = kf * 8 + tig;
        qa[kf][0] = __float_as_uint(Qb[(size_t)(qw + grp) * DD + cl]);
        qa[kf][1] = __float_as_uint(Qb[(size_t)(qw + grp + 8) * DD + cl]);
        qa[kf][2] = __float_as_uint(Qb[(size_t)(qw + grp) * DD + cl + 4]);
        qa[kf][3] = __float_as_uint(Qb[(size_t)(qw + grp + 8) * DD + cl + 4]);
    }

    float m0 = -3.4e38f, m1 = -3.4e38f, l0 = 0.f, l1 = 0.f;
    float oacc[4][4];
    #pragma unroll
    for (int nt = 0; nt < 4; nt++)
        #pragma unroll
        for (int r = 0; r < 4; r++) oacc[nt][r] = 0.f;

    const uint32_t* bm0 = g_bmask + (size_t)(qw + grp) * 16;
    const uint32_t* bm1 = g_bmask + (size_t)(qw + grp + 8) * 16;

    uint32_t sbase = (uint32_t)__cvta_generic_to_shared(sm);

    // prologue: stage chunk 0 into buffer 0 (raw copies)
    #pragma unroll
    for (int t = 0; t < 2; t++) {
        int i = tid + t * 256;
        int r = i >> 3, f = (i & 7) * 4;
        cp16(sbase + (r * KV_W + f) * 4, Kb + (size_t)r * DD + f);
        cp16(sbase + (64 * KV_W + r * KV_W + f) * 4, Vb + (size_t)r * DD + f);
    }
    CP_COMMIT();

    int srclane = (lane & 28) | (tig >> 1);
    bool oddt = (tig & 1) != 0;

    for (int ci = 0; ci < 8; ci++) {
        CP_WAIT0();
        __syncthreads();

        if (ci + 1 < 8) {
            int c1  = (ci + 1) * 64;
            uint32_t dst = sbase + ((ci + 1) & 1) * KVBUF * 4;
            #pragma unroll
            for (int t = 0; t < 2; t++) {
                int i = tid + t * 256;
                int r = i >> 3, f = (i & 7) * 4;
                cp16(dst + (r * KV_W + f) * 4, Kb + (size_t)(c1 + r) * DD + f);
                cp16(dst + (64 * KV_W + r * KV_W + f) * 4,
                     Vb + (size_t)(c1 + r) * DD + f);
            }
            CP_COMMIT();
        }

        const uint32_t* Ks = sm + (ci & 1) * KVBUF;
        const uint32_t* Vs = Ks + 64 * KV_W;
        int c0 = ci * 64;

        // S = Q K^T (unscaled)
        float sacc[8][4];
        #pragma unroll
        for (int nt = 0; nt < 8; nt++)
            #pragma unroll
            for (int r = 0; r < 4; r++) sacc[nt][r] = 0.f;
        #pragma unroll
        for (int nt = 0; nt < 8; nt++)
            #pragma unroll
            for (int kf = 0; kf < 4; kf++) {
                uint32_t b0v = Ks[(nt * 8 + grp) * KV_W + kf * 8 + tig];
                uint32_t b1v = Ks[(nt * 8 + grp) * KV_W + kf * 8 + tig + 4];
                mma_tf32(sacc[nt], qa[kf], b0v, b1v);
            }

        // mask + chunk max (unscaled domain)
        uint32_t wa0 = bm0[c0 >> 5], wa1 = bm0[(c0 >> 5) + 1];
        uint32_t wb0 = bm1[c0 >> 5], wb1 = bm1[(c0 >> 5) + 1];
        float cm0 = -3.4e38f, cm1 = -3.4e38f;
        #pragma unroll
        for (int nt = 0; nt < 8; nt++) {
            int j  = nt * 8 + 2 * tig;
            uint32_t wa = (j < 32) ? wa0 : wa1;
            uint32_t wb = (j < 32) ? wb0 : wb1;
            int sh = j & 31;
            if (!((wa >> sh) & 1))        sacc[nt][0] = -1e10f;
            if (!((wa >> (sh + 1)) & 1))  sacc[nt][1] = -1e10f;
            if (!((wb >> sh) & 1))        sacc[nt][2] = -1e10f;
            if (!((wb >> (sh + 1)) & 1))  sacc[nt][3] = -1e10f;
            cm0 = fmaxf(cm0, fmaxf(sacc[nt][0], sacc[nt][1]));
            cm1 = fmaxf(cm1, fmaxf(sacc[nt][2], sacc[nt][3]));
        }
        cm0 = fmaxf(cm0, __shfl_xor_sync(0xffffffffu, cm0, 1));
        cm0 = fmaxf(cm0, __shfl_xor_sync(0xffffffffu, cm0, 2));
        cm1 = fmaxf(cm1, __shfl_xor_sync(0xffffffffu, cm1, 1));
        cm1 = fmaxf(cm1, __shfl_xor_sync(0xffffffffu, cm1, 2));

        float nm0 = fmaxf(m0, cm0), nm1 = fmaxf(m1, cm1);
        float f0 = __expf((m0 - nm0) * escale), f1 = __expf((m1 - nm1) * escale);
        l0 *= f0; l1 *= f1;
        #pragma unroll
        for (int nt = 0; nt < 4; nt++) {
            oacc[nt][0] *= f0; oacc[nt][1] *= f0;
            oacc[nt][2] *= f1; oacc[nt][3] *= f1;
        }
        m0 = nm0; m1 = nm1;

        // per k-frag: exp -> tf32 -> shuffle c-frag->a-frag (dest-parity select)
        #pragma unroll
        for (int kb = 0; kb < 8; kb++) {
            float p0 = __expf((sacc[kb][0] - nm0) * escale);
            float p1 = __expf((sacc[kb][1] - nm0) * escale);
            float p2 = __expf((sacc[kb][2] - nm1) * escale);
            float p3 = __expf((sacc[kb][3] - nm1) * escale);
            l0 += p0 + p1; l1 += p2 + p3;
            uint32_t u0 = f2tf32(p0), u1 = f2tf32(p1);
            uint32_t u2 = f2tf32(p2), u3 = f2tf32(p3);
            // source lane s holds cols {2*(tig>>1), +1}; select by DEST parity
            uint32_t a0e = __shfl_sync(0xffffffffu, u0, srclane);
            uint32_t a0o = __shfl_sync(0xffffffffu, u1, srclane);
            uint32_t a1e = __shfl_sync(0xffffffffu, u2, srclane);
            uint32_t a1o = __shfl_sync(0xffffffffu, u3, srclane);
            uint32_t a2e = __shfl_sync(0xffffffffu, u0, srclane + 2);
            uint32_t a2o = __shfl_sync(0xffffffffu, u1, srclane + 2);
            uint32_t a3e = __shfl_sync(0xffffffffu, u2, srclane + 2);
            uint32_t a3o = __shfl_sync(0xffffffffu, u3, srclane + 2);
            uint32_t pa[4];
            pa[0] = oddt ? a0o : a0e;
            pa[1] = oddt ? a1o : a1e;
            pa[2] = oddt ? a2o : a2e;
            pa[3] = oddt ? a3o : a3e;
            #pragma unroll
            for (int nt = 0; nt < 4; nt++) {
                uint32_t b0v = Vs[(kb * 8 + tig) * KV_W + nt * 8 + grp];
                uint32_t b1v = Vs[(kb * 8 + tig + 4) * KV_W + nt * 8 + grp];
                mma_tf32(oacc[nt], pa, b0v, b1v);
            }
        }
    }

    l0 += __shfl_xor_sync(0xffffffffu, l0, 1);
    l0 += __shfl_xor_sync(0xffffffffu, l0, 2);
    l1 += __shfl_xor_sync(0xffffffffu, l1, 1);
    l1 += __shfl_xor_sync(0xffffffffu, l1, 2);
    float inv0 = 1.f / l0, inv1 = 1.f / l1;

    float* o0 = out + ((size_t)b * NN + qw + grp) * DD + h * HDIM;
    float* o1 = out + ((size_t)b * NN + qw + grp + 8) * DD + h * HDIM;
    #pragma unroll
    for (int nt = 0; nt < 4; nt++) {
        int cl = nt * 8 + 2 * tig;
        float2 v0 = {oacc[nt][0] * inv0, oacc[nt][1] * inv0};
        float2 v1 = {oacc[nt][2] * inv1, oacc[nt][3] * inv1};
        *(float2*)(o0 + cl) = v0;
        *(float2*)(o1 + cl) = v1;
    }
}

// ---------------- launch ------------------------------------------------------
extern "C" void kernel_launch(void* const* d_in, const int* in_sizes, int n_in,
                              void* d_out, int out_size) {
    const float* query = (const float*)d_in[0];
    const float* key   = (const float*)d_in[1];
    const float* value = (const float*)d_in[2];
    const int*   edge  = (const int*)d_in[3];
    const int*   mask  = (const int*)d_in[4];
    const float* Wq = (const float*)d_in[5];
    const float* bq = (const float*)d_in[6];
    const float* Wk = (const float*)d_in[7];
    const float* bk = (const float*)d_in[8];
    const float* Wv = (const float*)d_in[9];
    const float* bv = (const float*)d_in[10];
    const float* Wo = (const float*)d_in[11];
    const float* bo = (const float*)d_in[12];
    float* out = (float*)d_out;

    float *xwq, *xwk, *xwv, *Qp, *Kp, *Vp, *att;
    cudaGetSymbolAddress((void**)&xwq, g_xwq);
    cudaGetSymbolAddress((void**)&xwk, g_xwk);
    cudaGetSymbolAddress((void**)&xwv, g_xwv);
    cudaGetSymbolAddress((void**)&Qp,  g_Q);
    cudaGetSymbolAddress((void**)&Kp,  g_K);
    cudaGetSymbolAddress((void**)&Vp,  g_V);
    cudaGetSymbolAddress((void**)&att, g_att);

    cudaFuncSetAttribute(k_attn, cudaFuncAttributeMaxDynamicSharedMemorySize,
                         ATT_SMEM);
    cudaFuncSetAttribute(k_agg_gemm, cudaFuncAttributeMaxDynamicSharedMemorySize,
                         AGG_SMEM);

    // 1: graph prep + dense adjacency fill (unrounded)
    k_graph<<<1, NN>>>(edge);

    // 2: fused QKV projection (+z=3 service slice: round A, pack mask)
    k_gemm_mma<<<dim3(2, 128, 4), 256>>>(query, key, value,
                                         Wq, Wk, Wv,
                                         xwq, xwk, xwv, nullptr, mask, 1);

    // 3: aggregation GEMM (+bias, tf32-rounded outputs)
    k_agg_gemm<<<dim3(2, 4, 96), 256, AGG_SMEM>>>(xwq, xwk, xwv,
                                                  bq, bk, bv, Qp, Kp, Vp);

    // 4: flash attention, cp.async pipelined  (<- ncu capture slot)
    k_attn<<<dim3(4, HH, BB), 256, ATT_SMEM>>>(Qp, Kp, Vp, att);

    // 5: output projection (+bias, fp32 epilogue) into d_out
    k_gemm_mma<<<dim3(2, 128, 1), 256>>>(att, att, att,
                                         Wo, Wo, Wo,
                                         out, out, out, bo, nullptr, 0);
}

// round 13
// speedup vs baseline: 2.1547x; 1.0950x over previous
#include <cuda_runtime.h>
#include <cuda_fp16.h>
#include <cstdint>

#define BB   32
#define NN   512
#define DD   256
#define HH   8
#define HDIM 32
#define EE   16384
#define ETOT (EE + NN)

// ---------------- scratch (static device globals; no allocation) -------------
__device__ float    g_xwq[BB * NN * DD];
__device__ float    g_xwk[BB * NN * DD];
__device__ float    g_xwv[BB * NN * DD];
__device__ float    g_Q  [BB * NN * DD];
__device__ float    g_K  [BB * NN * DD];
__device__ float    g_V  [BB * NN * DD];
__device__ float    g_att[BB * NN * DD];
__device__ int      g_rowptr[NN + 1];
__device__ int2     g_edge[ETOT];           // (src, norm-as-int)
__device__ uint32_t g_bmask[NN * 16];       // packed mask bits
__device__ float    g_A[NN * NN];           // dense normalized adjacency
__device__ uint32_t g_Vh[BB * 256 * 256];   // half2-paired V: (b, kvpair, d)

// ---------------- helpers -----------------------------------------------------
__device__ __forceinline__ uint32_t f2tf32(float f) {
    uint32_t r;
    asm("cvt.rna.tf32.f32 %0, %1;" : "=r"(r) : "f"(f));
    return r;
}
__device__ __forceinline__ void mma_tf32(float* c, const uint32_t* a,
                                         uint32_t b0, uint32_t b1) {
    asm volatile(
        "mma.sync.aligned.m16n8k8.row.col.f32.tf32.tf32.f32 "
        "{%0,%1,%2,%3}, {%4,%5,%6,%7}, {%8,%9}, {%0,%1,%2,%3};"
        : "+f"(c[0]), "+f"(c[1]), "+f"(c[2]), "+f"(c[3])
        : "r"(a[0]), "r"(a[1]), "r"(a[2]), "r"(a[3]), "r"(b0), "r"(b1));
}
__device__ __forceinline__ void mma_f16(float* c, const uint32_t* a,
                                        uint32_t b0, uint32_t b1) {
    asm volatile(
        "mma.sync.aligned.m16n8k16.row.col.f32.f16.f16.f32 "
        "{%0,%1,%2,%3}, {%4,%5,%6,%7}, {%8,%9}, {%0,%1,%2,%3};"
        : "+f"(c[0]), "+f"(c[1]), "+f"(c[2]), "+f"(c[3])
        : "r"(a[0]), "r"(a[1]), "r"(a[2]), "r"(a[3]), "r"(b0), "r"(b1));
}
__device__ __forceinline__ uint32_t h2bits(float a, float b) {
    __half2 h = __floats2half2_rn(a, b);
    return *reinterpret_cast<uint32_t*>(&h);
}
__device__ __forceinline__ void cp16(uint32_t saddr, const void* g) {
    asm volatile("cp.async.ca.shared.global [%0], [%1], 16;"
                 :: "r"(saddr), "l"(g) : "memory");
}
#define CP_COMMIT() asm volatile("cp.async.commit_group;" ::: "memory")
#define CP_WAIT0()  asm volatile("cp.async.wait_group 0;" ::: "memory")

// ---------------- prep: zero dense A + pack mask (full grid) ------------------
__global__ void k_prep(const int* __restrict__ mask) {
    int idx = blockIdx.x * 256 + threadIdx.x;      // 65536
    ((float4*)g_A)[idx] = make_float4(0.f, 0.f, 0.f, 0.f);
    if (idx < NN * 16) {
        int r  = idx >> 4;
        int wd = idx & 15;
        const int* mrow = mask + (size_t)r * NN + wd * 32;
        uint32_t bits = 0;
        #pragma unroll
        for (int j = 0; j < 32; j++) bits |= (mrow[j] ? 1u : 0u) << j;
        g_bmask[idx] = bits;
    }
}

// ---------------- fused single-CTA graph prep + dense A fill ------------------
__global__ __launch_bounds__(NN) void k_graph(const int* __restrict__ edge) {
    __shared__ int sdeg[NN];
    __shared__ int scnt[NN];
    __shared__ int srow[NN];
    __shared__ int ss[NN];
    __shared__ int se64;
    int t = threadIdx.x;

    if (t == 0) {
        int nz = 0;
        for (int i = 0; i < 64; i++) nz += (edge[2 * i + 1] != 0);
        se64 = (nz == 0) ? 1 : 0;
    }
    sdeg[t] = 0;
    scnt[t] = 0;
    __syncthreads();
    int e64 = se64;

    for (int e = t; e < ETOT; e += NN) {
        int dst = (e < EE) ? (e64 ? edge[2 * (EE + e)] : edge[EE + e]) : (e - EE);
        if (dst >= 0 && dst < NN) atomicAdd(&sdeg[dst], 1);
    }
    __syncthreads();

    ss[t] = sdeg[t];
    __syncthreads();
    for (int off = 1; off < NN; off <<= 1) {
        int v = (t >= off) ? ss[t - off] : 0;
        __syncthreads();
        ss[t] += v;
        __syncthreads();
    }
    srow[t] = ss[t] - sdeg[t];
    g_rowptr[t + 1] = ss[t];
    if (t == 0) g_rowptr[0] = 0;
    __syncthreads();

    for (int e = t; e < ETOT; e += NN) {
        int s, d;
        if (e < EE) {
            s = e64 ? edge[2 * e] : edge[e];
            d = e64 ? edge[2 * (EE + e)] : edge[EE + e];
        } else {
            s = e - EE; d = e - EE;
        }
        if (s < 0 || s >= NN || d < 0 || d >= NN) continue;
        float nm = rsqrtf((float)sdeg[s]) * rsqrtf((float)sdeg[d]);
        int pos = srow[d] + atomicAdd(&scnt[d], 1);
        g_edge[pos] = make_int2(s, __float_as_int(nm));
    }
    __syncthreads();

    // per-row serial edge fill into pre-zeroed A (deterministic)
    float* arow = g_A + (size_t)t * NN;
    for (int i = srow[t]; i < ss[t]; i++) {
        int2 e = g_edge[i];
        arow[e.x] += __int_as_float(e.y);
    }
}

// ---------------- tf32 mma.sync GEMM + service slice (round A) ----------------
#define AS_STRIDE 36
#define BS_STRIDE 132

__global__ __launch_bounds__(256) void k_gemm_mma(
    const float* __restrict__ a0p, const float* __restrict__ a1p,
    const float* __restrict__ a2p,
    const float* __restrict__ w0, const float* __restrict__ w1,
    const float* __restrict__ w2,
    float* __restrict__ c0p, float* __restrict__ c1p, float* __restrict__ c2p,
    const float* __restrict__ bias, int roundC)
{
    const int z = blockIdx.z;
    int tid = threadIdx.x;

    if (z == 3) {
        // service CTAs: round dense A to tf32 (coalesced, full grid slice)
        int cta = blockIdx.x * 128 + blockIdx.y;    // 0..255
        int i4  = cta * 256 + tid;                  // 65536 float4s
        float4* a4 = (float4*)g_A;
        float4 v = a4[i4];
        v.x = __uint_as_float(f2tf32(v.x));
        v.y = __uint_as_float(f2tf32(v.y));
        v.z = __uint_as_float(f2tf32(v.z));
        v.w = __uint_as_float(f2tf32(v.w));
        a4[i4] = v;
        return;
    }

    __shared__ uint32_t As[128 * AS_STRIDE];
    __shared__ uint32_t Bs[32 * BS_STRIDE];
    __shared__ float    bsh[128];

    const float* A  = (z == 0) ? a0p : (z == 1) ? a1p : a2p;
    const float* Wm = (z == 0) ? w0  : (z == 1) ? w1  : w2;
    float*       C  = (z == 0) ? c0p : (z == 1) ? c1p : c2p;

    const int n0 = blockIdx.x * 128;
    const int m0 = blockIdx.y * 128;

    int wid  = tid >> 5;
    int lane = tid & 31;
    int grp  = lane >> 2;
    int tig  = lane & 3;
    int wm   = (wid & 1) * 64;
    int wn   = (wid >> 1) * 32;

    if (tid < 128) bsh[tid] = bias ? bias[n0 + tid] : 0.f;

    float acc[4][4][4];
    #pragma unroll
    for (int i = 0; i < 4; i++)
        #pragma unroll
        for (int j = 0; j < 4; j++)
            #pragma unroll
            for (int r = 0; r < 4; r++) acc[i][j][r] = 0.f;

    for (int k0 = 0; k0 < 256; k0 += 32) {
        #pragma unroll
        for (int t = 0; t < 4; t++) {
            int i   = tid + t * 256;
            int row = i >> 3;
            int q   = (i & 7) * 4;
            float4 v = *(const float4*)(A + (size_t)(m0 + row) * 256 + k0 + q);
            uint4 u;
            u.x = f2tf32(v.x); u.y = f2tf32(v.y);
            u.z = f2tf32(v.z); u.w = f2tf32(v.w);
            *(uint4*)(As + row * AS_STRIDE + q) = u;
        }
        #pragma unroll
        for (int t = 0; t < 4; t++) {
            int i = tid + t * 256;
            int k = i >> 5;
            int q = (i & 31) * 4;
            float4 v = *(const float4*)(Wm + (size_t)(k0 + k) * 256 + n0 + q);
            uint4 u;
            u.x = f2tf32(v.x); u.y = f2tf32(v.y);
            u.z = f2tf32(v.z); u.w = f2tf32(v.w);
            *(uint4*)(Bs + k * BS_STRIDE + q) = u;
        }
        __syncthreads();

        #pragma unroll
        for (int ks = 0; ks < 4; ks++) {
            int kk = ks * 8;
            uint32_t af[4][4], bf[4][2];
            #pragma unroll
            for (int mt = 0; mt < 4; mt++) {
                int r = wm + mt * 16 + grp;
                af[mt][0] = As[r * AS_STRIDE + kk + tig];
                af[mt][1] = As[(r + 8) * AS_STRIDE + kk + tig];
                af[mt][2] = As[r * AS_STRIDE + kk + tig + 4];
                af[mt][3] = As[(r + 8) * AS_STRIDE + kk + tig + 4];
            }
            #pragma unroll
            for (int nt = 0; nt < 4; nt++) {
                int c = wn + nt * 8 + grp;
                bf[nt][0] = Bs[(kk + tig) * BS_STRIDE + c];
                bf[nt][1] = Bs[(kk + tig + 4) * BS_STRIDE + c];
            }
            #pragma unroll
            for (int mt = 0; mt < 4; mt++)
                #pragma unroll
                for (int nt = 0; nt < 4; nt++)
                    mma_tf32(acc[mt][nt], af[mt], bf[nt][0], bf[nt][1]);
        }
        __syncthreads();
    }

    #pragma unroll
    for (int mt = 0; mt < 4; mt++) {
        #pragma unroll
        for (int nt = 0; nt < 4; nt++) {
            int cc = wn + nt * 8 + tig * 2;
            float b0 = bsh[cc], b1 = bsh[cc + 1];
            size_t r0 = (size_t)(m0 + wm + mt * 16 + grp) * 256 + n0 + cc;
            size_t r1 = r0 + 8 * 256;
            float2 v0 = {acc[mt][nt][0] + b0, acc[mt][nt][1] + b1};
            float2 v1 = {acc[mt][nt][2] + b0, acc[mt][nt][3] + b1};
            if (roundC) {
                v0.x = __uint_as_float(f2tf32(v0.x));
                v0.y = __uint_as_float(f2tf32(v0.y));
                v1.x = __uint_as_float(f2tf32(v1.x));
                v1.y = __uint_as_float(f2tf32(v1.y));
            }
            *(float2*)(C + r0) = v0;
            *(float2*)(C + r1) = v1;
        }
    }
}

// ---------------- aggregation GEMM, cp.async 2-stage; outputs tf32-rounded ----
#define AGG_ABUF (128 * AS_STRIDE)
#define AGG_BBUF (32 * BS_STRIDE)
#define AGG_SMEM ((2 * AGG_ABUF + 2 * AGG_BBUF + 128) * 4)

__global__ __launch_bounds__(256) void k_agg_gemm(
    const float* __restrict__ xq, const float* __restrict__ xk,
    const float* __restrict__ xv,
    const float* __restrict__ bq, const float* __restrict__ bk,
    const float* __restrict__ bv,
    float* __restrict__ oq, float* __restrict__ ok_, float* __restrict__ ov)
{
    extern __shared__ uint32_t dsm[];
    uint32_t* Asb = dsm;
    uint32_t* Bsb = dsm + 2 * AGG_ABUF;
    float*    bsh = (float*)(dsm + 2 * AGG_ABUF + 2 * AGG_BBUF);

    int zz = blockIdx.z;
    int z  = zz >> 5;
    int b  = zz & 31;
    const float* X    = (z == 0) ? xq : (z == 1) ? xk : xv;
    const float* bias = (z == 0) ? bq : (z == 1) ? bk : bv;
    float*       O    = (z == 0) ? oq : (z == 1) ? ok_ : ov;
    const float* Xb = X + (size_t)b * NN * DD;
    float*       Cb = O + (size_t)b * NN * DD;

    const int n0 = blockIdx.x * 128;
    const int m0 = blockIdx.y * 128;

    int tid  = threadIdx.x;
    int wid  = tid >> 5;
    int lane = tid & 31;
    int grp  = lane >> 2;
    int tig  = lane & 3;
    int wm   = (wid & 1) * 64;
    int wn   = (wid >> 1) * 32;

    if (tid < 128) bsh[tid] = bias[n0 + tid];

    uint32_t sA = (uint32_t)__cvta_generic_to_shared(Asb);
    uint32_t sB = (uint32_t)__cvta_generic_to_shared(Bsb);

    float acc[4][4][4];
    #pragma unroll
    for (int i = 0; i < 4; i++)
        #pragma unroll
        for (int j = 0; j < 4; j++)
            #pragma unroll
            for (int r = 0; r < 4; r++) acc[i][j][r] = 0.f;

    #pragma unroll
    for (int t = 0; t < 4; t++) {
        int i = tid + t * 256;
        int row = i >> 3, q = (i & 7) * 4;
        cp16(sA + (row * AS_STRIDE + q) * 4, g_A + (size_t)(m0 + row) * NN + q);
    }
    #pragma unroll
    for (int t = 0; t < 4; t++) {
        int i = tid + t * 256;
        int k = i >> 5, q = (i & 31) * 4;
        cp16(sB + (k * BS_STRIDE + q) * 4, Xb + (size_t)k * 256 + n0 + q);
    }
    CP_COMMIT();

    for (int c = 0; c < 16; c++) {
        CP_WAIT0();
        __syncthreads();

        if (c + 1 < 16) {
            int k0  = (c + 1) * 32;
            int buf = (c + 1) & 1;
            uint32_t dA = sA + buf * AGG_ABUF * 4;
            uint32_t dB = sB + buf * AGG_BBUF * 4;
            #pragma unroll
            for (int t = 0; t < 4; t++) {
                int i = tid + t * 256;
                int row = i >> 3, q = (i & 7) * 4;
                cp16(dA + (row * AS_STRIDE + q) * 4,
                     g_A + (size_t)(m0 + row) * NN + k0 + q);
            }
            #pragma unroll
            for (int t = 0; t < 4; t++) {
                int i = tid + t * 256;
                int k = i >> 5, q = (i & 31) * 4;
                cp16(dB + (k * BS_STRIDE + q) * 4,
                     Xb + (size_t)(k0 + k) * 256 + n0 + q);
            }
            CP_COMMIT();
        }

        const uint32_t* As = Asb + (c & 1) * AGG_ABUF;
        const uint32_t* Bs = Bsb + (c & 1) * AGG_BBUF;

        #pragma unroll
        for (int ks = 0; ks < 4; ks++) {
            int kk = ks * 8;
            uint32_t af[4][4], bf[4][2];
            #pragma unroll
            for (int mt = 0; mt < 4; mt++) {
                int r = wm + mt * 16 + grp;
                af[mt][0] = As[r * AS_STRIDE + kk + tig];
                af[mt][1] = As[(r + 8) * AS_STRIDE + kk + tig];
                af[mt][2] = As[r * AS_STRIDE + kk + tig + 4];
                af[mt][3] = As[(r + 8) * AS_STRIDE + kk + tig + 4];
            }
            #pragma unroll
            for (int nt = 0; nt < 4; nt++) {
                int cc = wn + nt * 8 + grp;
                bf[nt][0] = Bs[(kk + tig) * BS_STRIDE + cc];
                bf[nt][1] = Bs[(kk + tig + 4) * BS_STRIDE + cc];
            }
            #pragma unroll
            for (int mt = 0; mt < 4; mt++)
                #pragma unroll
                for (int nt = 0; nt < 4; nt++)
                    mma_tf32(acc[mt][nt], af[mt], bf[nt][0], bf[nt][1]);
        }
        __syncthreads();
    }

    #pragma unroll
    for (int mt = 0; mt < 4; mt++) {
        #pragma unroll
        for (int nt = 0; nt < 4; nt++) {
            int cc = wn + nt * 8 + tig * 2;
            float b0 = bsh[cc], b1 = bsh[cc + 1];
            size_t r0 = (size_t)(m0 + wm + mt * 16 + grp) * 256 + n0 + cc;
            size_t r1 = r0 + 8 * 256;
            float2 v0, v1;
            v0.x = __uint_as_float(f2tf32(acc[mt][nt][0] + b0));
            v0.y = __uint_as_float(f2tf32(acc[mt][nt][1] + b1));
            v1.x = __uint_as_float(f2tf32(acc[mt][nt][2] + b0));
            v1.y = __uint_as_float(f2tf32(acc[mt][nt][3] + b1));
            *(float2*)(Cb + r0) = v0;
            *(float2*)(Cb + r1) = v1;
        }
    }
}

// ---------------- V -> half2-paired copy (g_V -> g_Vh) ------------------------
__global__ void k_vh() {
    int idx = blockIdx.x * 256 + threadIdx.x;     // 524288
    int dq = (idx & 63) * 4;
    int p  = (idx >> 6) & 255;
    int b  = idx >> 14;
    const float* v0 = g_V + ((size_t)b * NN + 2 * p) * DD + dq;
    float4 x0 = *(const float4*)v0;
    float4 x1 = *(const float4*)(v0 + DD);
    uint4 o;
    o.x = h2bits(x0.x, x1.x);
    o.y = h2bits(x0.y, x1.y);
    o.z = h2bits(x0.z, x1.z);
    o.w = h2bits(x0.w, x1.w);
    *(uint4*)(g_Vh + ((size_t)(b * 256 + p) * 256 + dq)) = o;
}

// ---------------- flash attention: tf32 QK + fp16 PV (shuffle-free) -----------
#define KW      36
#define KWORDS  (64 * KW)
#define VWORDS  (32 * KW)
#define BUFW    (KWORDS + VWORDS)
#define ATT_SMEM (2 * BUFW * 4)

__global__ __launch_bounds__(256, 2) void k_attn(
    const float* __restrict__ Q, const float* __restrict__ K,
    float* __restrict__ out)
{
    extern __shared__ uint32_t sm[];

    int h   = blockIdx.y;
    int b   = blockIdx.z;
    int tid = threadIdx.x;
    int wid = tid >> 5, lane = tid & 31;
    int grp = lane >> 2, tig = lane & 3;
    int qw  = blockIdx.x * 128 + wid * 16;

    const float* Qb = Q + (size_t)b * NN * DD + h * HDIM;
    const float* Kb = K + (size_t)b * NN * DD + h * HDIM;

    const float escale = 0.17677669529663687f;   // 1/sqrt(HD)

    uint32_t qa[4][4];
    #pragma unroll
    for (int kf = 0; kf < 4; kf++) {
        int cl = kf * 8 + tig;
        qa[kf][0] = __float_as_uint(Qb[(size_t)(qw + grp) * DD + cl]);
        qa[kf][1] = __float_as_uint(Qb[(size_t)(qw + grp + 8) * DD + cl]);
        qa[kf][2] = __float_as_uint(Qb[(size_t)(qw + grp) * DD + cl + 4]);
        qa[kf][3] = __float_as_uint(Qb[(size_t)(qw + grp + 8) * DD + cl + 4]);
    }

    float m0 = -3.4e38f, m1 = -3.4e38f, l0 = 0.f, l1 = 0.f;
    float oacc[4][4];
    #pragma unroll
    for (int nt = 0; nt < 4; nt++)
        #pragma unroll
        for (int r = 0; r < 4; r++) oacc[nt][r] = 0.f;

    const uint32_t* bm0 = g_bmask + (size_t)(qw + grp) * 16;
    const uint32_t* bm1 = g_bmask + (size_t)(qw + grp + 8) * 16;

    uint32_t sbase = (uint32_t)__cvta_generic_to_shared(sm);
    int vp = tid >> 3, vq = (tid & 7) * 4;

    // prologue: stage chunk 0
    #pragma unroll
    for (int t = 0; t < 2; t++) {
        int i = tid + t * 256;
        int r = i >> 3, f = (i & 7) * 4;
        cp16(sbase + (r * KW + f) * 4, Kb + (size_t)r * DD + f);
    }
    cp16(sbase + (KWORDS + vp * KW + vq) * 4,
         g_Vh + (size_t)(b * 256 + vp) * 256 + h * HDIM + vq);
    CP_COMMIT();

    for (int ci = 0; ci < 8; ci++) {
        CP_WAIT0();
        __syncthreads();

        if (ci + 1 < 8) {
            int c1  = (ci + 1) * 64;
            uint32_t dst = sbase + ((ci + 1) & 1) * BUFW * 4;
            #pragma unroll
            for (int t = 0; t < 2; t++) {
                int i = tid + t * 256;
                int r = i >> 3, f = (i & 7) * 4;
                cp16(dst + (r * KW + f) * 4, Kb + (size_t)(c1 + r) * DD + f);
            }
            cp16(dst + (KWORDS + vp * KW + vq) * 4,
                 g_Vh + (size_t)(b * 256 + (ci + 1) * 32 + vp) * 256 + h * HDIM + vq);
            CP_COMMIT();
        }

        const uint32_t* Ks = sm + (ci & 1) * BUFW;
        const uint32_t* Vs = Ks + KWORDS;
        int c0 = ci * 64;

        // S = Q K^T (tf32, unscaled)
        float sacc[8][4];
        #pragma unroll
        for (int nt = 0; nt < 8; nt++)
            #pragma unroll
            for (int r = 0; r < 4; r++) sacc[nt][r] = 0.f;
        #pragma unroll
        for (int nt = 0; nt < 8; nt++)
            #pragma unroll
            for (int kf = 0; kf < 4; kf++) {
                uint32_t b0v = Ks[(nt * 8 + grp) * KW + kf * 8 + tig];
                uint32_t b1v = Ks[(nt * 8 + grp) * KW + kf * 8 + tig + 4];
                mma_tf32(sacc[nt], qa[kf], b0v, b1v);
            }

        // mask + chunk max
        uint32_t wa0 = bm0[c0 >> 5], wa1 = bm0[(c0 >> 5) + 1];
        uint32_t wb0 = bm1[c0 >> 5], wb1 = bm1[(c0 >> 5) + 1];
        float cm0 = -3.4e38f, cm1 = -3.4e38f;
        #pragma unroll
        for (int nt = 0; nt < 8; nt++) {
            int j  = nt * 8 + 2 * tig;
            uint32_t wa = (j < 32) ? wa0 : wa1;
            uint32_t wb = (j < 32) ? wb0 : wb1;
            int sh = j & 31;
            if (!((wa >> sh) & 1))        sacc[nt][0] = -1e10f;
            if (!((wa >> (sh + 1)) & 1))  sacc[nt][1] = -1e10f;
            if (!((wb >> sh) & 1))        sacc[nt][2] = -1e10f;
            if (!((wb >> (sh + 1)) & 1))  sacc[nt][3] = -1e10f;
            cm0 = fmaxf(cm0, fmaxf(sacc[nt][0], sacc[nt][1]));
            cm1 = fmaxf(cm1, fmaxf(sacc[nt][2], sacc[nt][3]));
        }
        cm0 = fmaxf(cm0, __shfl_xor_sync(0xffffffffu, cm0, 1));
        cm0 = fmaxf(cm0, __shfl_xor_sync(0xffffffffu, cm0, 2));
        cm1 = fmaxf(cm1, __shfl_xor_sync(0xffffffffu, cm1, 1));
        cm1 = fmaxf(cm1, __shfl_xor_sync(0xffffffffu, cm1, 2));

        float nm0 = fmaxf(m0, cm0), nm1 = fmaxf(m1, cm1);
        float f0 = __expf((m0 - nm0) * escale), f1 = __expf((m1 - nm1) * escale);
        l0 *= f0; l1 *= f1;
        #pragma unroll
        for (int nt = 0; nt < 4; nt++) {
            oacc[nt][0] *= f0; oacc[nt][1] *= f0;
            oacc[nt][2] *= f1; oacc[nt][3] *= f1;
        }
        m0 = nm0; m1 = nm1;

        // P in fp16 (c-frag layout == a-frag layout for k16: no shuffles)
        uint32_t h2a[8], h2b[8];
        #pragma unroll
        for (int nt = 0; nt < 8; nt++) {
            float p0 = __expf((sacc[nt][0] - nm0) * escale);
            float p1 = __expf((sacc[nt][1] - nm0) * escale);
            float p2 = __expf((sacc[nt][2] - nm1) * escale);
            float p3 = __expf((sacc[nt][3] - nm1) * escale);
            l0 += p0 + p1; l1 += p2 + p3;
            h2a[nt] = h2bits(p0, p1);
            h2b[nt] = h2bits(p2, p3);
        }

        // O += P V  (fp16 m16n8k16: 4 k-steps)
        #pragma unroll
        for (int s = 0; s < 4; s++) {
            uint32_t pa[4];
            pa[0] = h2a[2 * s];
            pa[1] = h2b[2 * s];
            pa[2] = h2a[2 * s + 1];
            pa[3] = h2b[2 * s + 1];
            #pragma unroll
            for (int nt = 0; nt < 4; nt++) {
                uint32_t b0v = Vs[(s * 8 + tig) * KW + nt * 8 + grp];
                uint32_t b1v = Vs[(s * 8 + tig + 4) * KW + nt * 8 + grp];
                mma_f16(oacc[nt], pa, b0v, b1v);
            }
        }
    }

    l0 += __shfl_xor_sync(0xffffffffu, l0, 1);
    l0 += __shfl_xor_sync(0xffffffffu, l0, 2);
    l1 += __shfl_xor_sync(0xffffffffu, l1, 1);
    l1 += __shfl_xor_sync(0xffffffffu, l1, 2);
    float inv0 = 1.f / l0, inv1 = 1.f / l1;

    float* o0 = out + ((size_t)b * NN + qw + grp) * DD + h * HDIM;
    float* o1 = out + ((size_t)b * NN + qw + grp + 8) * DD + h * HDIM;
    #pragma unroll
    for (int nt = 0; nt < 4; nt++) {
        int cl = nt * 8 + 2 * tig;
        float2 v0 = {oacc[nt][0] * inv0, oacc[nt][1] * inv0};
        float2 v1 = {oacc[nt][2] * inv1, oacc[nt][3] * inv1};
        *(float2*)(o0 + cl) = v0;
        *(float2*)(o1 + cl) = v1;
    }
}

// ---------------- launch ------------------------------------------------------
extern "C" void kernel_launch(void* const* d_in, const int* in_sizes, int n_in,
                              void* d_out, int out_size) {
    const float* query = (const float*)d_in[0];
    const float* key   = (const float*)d_in[1];
    const float* value = (const float*)d_in[2];
    const int*   edge  = (const int*)d_in[3];
    const int*   mask  = (const int*)d_in[4];
    const float* Wq = (const float*)d_in[5];
    const float* bq = (const float*)d_in[6];
    const float* Wk = (const float*)d_in[7];
    const float* bk = (const float*)d_in[8];
    const float* Wv = (const float*)d_in[9];
    const float* bv = (const float*)d_in[10];
    const float* Wo = (const float*)d_in[11];
    const float* bo = (const float*)d_in[12];
    float* out = (float*)d_out;

    float *xwq, *xwk, *xwv, *Qp, *Kp, *Vp, *att;
    cudaGetSymbolAddress((void**)&xwq, g_xwq);
    cudaGetSymbolAddress((void**)&xwk, g_xwk);
    cudaGetSymbolAddress((void**)&xwv, g_xwv);
    cudaGetSymbolAddress((void**)&Qp,  g_Q);
    cudaGetSymbolAddress((void**)&Kp,  g_K);
    cudaGetSymbolAddress((void**)&Vp,  g_V);
    cudaGetSymbolAddress((void**)&att, g_att);

    cudaFuncSetAttribute(k_attn, cudaFuncAttributeMaxDynamicSharedMemorySize,
                         ATT_SMEM);
    cudaFuncSetAttribute(k_agg_gemm, cudaFuncAttributeMaxDynamicSharedMemorySize,
                         AGG_SMEM);

    // 1: zero dense A + pack mask (full grid)
    k_prep<<<256, 256>>>(mask);

    // 2: graph prep + dense adjacency fill (single CTA)
    k_graph<<<1, NN>>>(edge);

    // 3: fused QKV projection (+z=3 service slice: round A)
    k_gemm_mma<<<dim3(2, 128, 4), 256>>>(query, key, value,
                                         Wq, Wk, Wv,
                                         xwq, xwk, xwv, nullptr, 1);

    // 4: aggregation GEMM (+bias, tf32-rounded outputs)  (<- ncu capture slot)
    k_agg_gemm<<<dim3(2, 4, 96), 256, AGG_SMEM>>>(xwq, xwk, xwv,
                                                  bq, bk, bv, Qp, Kp, Vp);

    // 5: pair V into half2 (g_V -> g_Vh)
    k_vh<<<2048, 256>>>();

    // 6: flash attention (tf32 QK + fp16 PV)
    k_attn<<<dim3(4, HH, BB), 256, ATT_SMEM>>>(Qp, Kp, att);

    // 7: output projection (+bias, fp32 epilogue) into d_out
    k_gemm_mma<<<dim3(2, 128, 1), 256>>>(att, att, att,
                                         Wo, Wo, Wo,
                                         out, out, out, bo, 0);
}